// round 8
// baseline (speedup 1.0000x reference)
#include <cuda_runtime.h>
#include <math.h>
#include <stdint.h>

// Problem constants
#define B_   16
#define L_   50
#define P_   49
#define T_   20
#define D_   512
#define H_   8
#define DH_  64
#define DFF_ 2048
#define IMG_TOK (B_*L_*T_)   // 16000  (= 125 tiles of 128, exactly)
#define TIT_TOK (B_*L_*P_)   // 39200
#define NTOK (IMG_TOK + TIT_TOK)  // 55200
#define NEGV (-1000000000.0f)
#define EPS_ 1e-6f

// ---------------- scratch ----------------
__device__ uint32_t g_attn_t[NTOK * D_];              // attention out, tf32 bits
__device__ float    g_hid   [NTOK * D_];              // proj out fp32 (residual)
__device__ uint32_t g_hid_t [NTOK * D_];              // proj out tf32 (FFN1 input)
__device__ uint32_t g_ffn1_t[(size_t)NTOK * DFF_];    // gelu out tf32 (FFN2 input)
__device__ float    g_ffn2  [NTOK * D_];              // FFN2 out fp32 (LN input)

// pre-converted weights (tf32 bits), packed segments
#define WOFF_PROJ 0
#define WOFF_W1I  (512*512)
#define WOFF_W1T  (WOFF_W1I + 2048*512)
#define WOFF_W2I  (WOFF_W1T + 2048*512)
#define WOFF_W2T  (WOFF_W2I + 512*2048)
#define WTOTAL    (WOFF_W2T + 512*2048)   // 4456448
__device__ uint32_t g_wbuf[WTOTAL];

__device__ __forceinline__ uint32_t f2tf32(float f) {
    uint32_t r; asm("cvt.rna.tf32.f32 %0, %1;" : "=r"(r) : "f"(f)); return r;
}
__device__ __forceinline__ float gelu_t(float x) {
    float x3 = x * x * x;
    float u = 0.7978845608028654f * (x + 0.044715f * x3);
    return 0.5f * x * (1.f + tanhf(u));
}
__device__ __forceinline__ void mma_tf32(float* c, const uint32_t* a, const uint32_t* b) {
    asm volatile(
        "mma.sync.aligned.m16n8k8.row.col.f32.tf32.tf32.f32 "
        "{%0,%1,%2,%3}, {%4,%5,%6,%7}, {%8,%9}, {%0,%1,%2,%3};"
        : "+f"(c[0]), "+f"(c[1]), "+f"(c[2]), "+f"(c[3])
        : "r"(a[0]), "r"(a[1]), "r"(a[2]), "r"(a[3]), "r"(b[0]), "r"(b[1]));
}
__device__ __forceinline__ void cp_async16(uint32_t dst, const void* src, uint32_t nbytes) {
    asm volatile("cp.async.cg.shared.global [%0], [%1], 16, %2;"
                 :: "r"(dst), "l"(src), "r"(nbytes));
}
__device__ __forceinline__ void cp_commit() {
    asm volatile("cp.async.commit_group;" ::: "memory");
}
template <int N>
__device__ __forceinline__ void cp_wait() {
    asm volatile("cp.async.wait_group %0;" :: "n"(N) : "memory");
}

// ---------------- weight pre-conversion (fp32 -> tf32 bits) ----------------
__global__ void __launch_bounds__(256) prep_w(
    const float* __restrict__ a0, const float* __restrict__ a1,
    const float* __restrict__ a2, const float* __restrict__ a3,
    const float* __restrict__ a4, uint32_t* __restrict__ o)
{
    size_t i = ((size_t)blockIdx.x * 256 + threadIdx.x) * 4;
    if (i >= WTOTAL) return;
    const float* src; size_t off;
    if      (i < WOFF_W1I) { src = a0; off = i; }
    else if (i < WOFF_W1T) { src = a1; off = i - WOFF_W1I; }
    else if (i < WOFF_W2I) { src = a2; off = i - WOFF_W1T; }
    else if (i < WOFF_W2T) { src = a3; off = i - WOFF_W2I; }
    else                   { src = a4; off = i - WOFF_W2T; }
    float4 v = *(const float4*)(src + off);
    uint4 u; u.x = f2tf32(v.x); u.y = f2tf32(v.y); u.z = f2tf32(v.z); u.w = f2tf32(v.w);
    *(uint4*)(o + i) = u;
}

// ---------------- tensor-core GEMM via mma.sync tf32 + 3-stage cp.async ----------------
// Operands are pre-converted tf32 bit patterns: NO cvt in the mainloop.
// C = A[M,K] @ Wsel[N,K]^T + bias (+GELU). One __syncthreads per K-chunk.
#define SROW 36                        // smem row stride (u32); row = 144 B, conflict-free
#define TILE_BYTES (128 * SROW * 4)    // 18432 B per matrix per stage
#define NSTAGE 3
#define MM_SMEM (NSTAGE * 2 * TILE_BYTES)   // 110592 B

__global__ void __launch_bounds__(256, 2) mma_gemm(
    const uint32_t* __restrict__ A,
    const uint32_t* __restrict__ W0, const float* __restrict__ b0,
    const uint32_t* __restrict__ W1, const float* __restrict__ b1,
    int split_tile,
    float* __restrict__ Cf, uint32_t* __restrict__ Ct,
    int M, int N, int K, int act)
{
    extern __shared__ uint32_t sh[];
    const uint32_t sm_base = (uint32_t)__cvta_generic_to_shared(sh);
    // stage s: A at sm_base + s*2*TILE, B at sm_base + s*2*TILE + TILE
    uint32_t aU[NSTAGE], bU[NSTAGE];
    const uint32_t *aF[NSTAGE], *bF[NSTAGE];
    #pragma unroll
    for (int s = 0; s < NSTAGE; s++) {
        aU[s] = sm_base + s * 2 * TILE_BYTES;
        bU[s] = aU[s] + TILE_BYTES;
        aF[s] = sh + (size_t)s * 2 * (TILE_BYTES / 4);
        bF[s] = aF[s] + TILE_BYTES / 4;
    }

    const int tid = threadIdx.x;
    const int m0 = blockIdx.y * 128, n0 = blockIdx.x * 128;
    const uint32_t* W  = (blockIdx.y < split_tile) ? W0 : W1;
    const float* bias  = (blockIdx.y < split_tile) ? b0 : b1;

    const int w = tid >> 5, lane = tid & 31;
    const int wm = w & 3, wn = w >> 2;          // warp tile: rows wm*32, cols wn*64
    const int group = lane >> 2, quad = lane & 3;

    const int lrow0 = tid >> 3;        // copy mapping: rows lrow0 + t*32
    const int lc4   = tid & 7;         // 16B column

    float acc[2][8][4];
    #pragma unroll
    for (int i = 0; i < 2; i++)
        #pragma unroll
        for (int j = 0; j < 8; j++)
            #pragma unroll
            for (int q = 0; q < 4; q++) acc[i][j][q] = 0.f;

    const int nch = K >> 5;

    auto issue = [&](int buf, int kc) {
        #pragma unroll
        for (int t = 0; t < 4; t++) {
            int row = lrow0 + t * 32;
            uint32_t off = (uint32_t)(row * 144 + lc4 * 16);
            size_t arow = (m0 + row < M) ? (size_t)(m0 + row) : 0;
            cp_async16(aU[buf] + off, A + arow * K + kc + lc4 * 4,
                       (m0 + row < M) ? 16u : 0u);
            cp_async16(bU[buf] + off, W + (size_t)(n0 + row) * K + kc + lc4 * 4, 16u);
        }
        cp_commit();
    };

    auto compute = [&](int buf) {
        const uint32_t* ap = aF[buf];
        const uint32_t* bp = bF[buf];
        #pragma unroll
        for (int ks = 0; ks < 4; ks++) {
            const int k0 = ks * 8;
            uint32_t afr[2][4];
            #pragma unroll
            for (int mi = 0; mi < 2; mi++) {
                int r = wm * 32 + mi * 16 + group;
                afr[mi][0] = ap[(r    ) * SROW + k0 + quad];
                afr[mi][1] = ap[(r + 8) * SROW + k0 + quad];
                afr[mi][2] = ap[(r    ) * SROW + k0 + quad + 4];
                afr[mi][3] = ap[(r + 8) * SROW + k0 + quad + 4];
            }
            uint32_t bfr[8][2];
            #pragma unroll
            for (int ni = 0; ni < 8; ni++) {
                int n = wn * 64 + ni * 8 + group;
                bfr[ni][0] = bp[n * SROW + k0 + quad];
                bfr[ni][1] = bp[n * SROW + k0 + quad + 4];
            }
            #pragma unroll
            for (int mi = 0; mi < 2; mi++)
                #pragma unroll
                for (int ni = 0; ni < 8; ni++)
                    mma_tf32(acc[mi][ni], afr[mi], bfr[ni]);
        }
    };

    // prologue: 2 stages in flight
    issue(0, 0);
    if (nch > 1) issue(1, 32); else cp_commit();

    // mainloop: ONE barrier per chunk; one group committed per iteration
    for (int c = 0; c < nch; c++) {
        cp_wait<1>();                // all groups except newest done => stage c landed
        __syncthreads();             // stage (c-1)%3 free for overwrite; stage c visible
        if (c + 2 < nch) {
            int s = c + 2; s -= (s >= NSTAGE) ? NSTAGE : 0; s -= (s >= NSTAGE) ? NSTAGE : 0;
            issue((c + 2) % NSTAGE, (c + 2) << 5);
        } else {
            cp_commit();             // empty group keeps wait<1> semantics uniform
        }
        compute(c % NSTAGE);
    }

    // epilogue: bias + optional GELU; fp32 and/or tf32 outputs
    #pragma unroll
    for (int ni = 0; ni < 8; ni++) {
        int cc = n0 + wn * 64 + ni * 8 + quad * 2;
        float2 b2 = *(const float2*)(bias + cc);
        #pragma unroll
        for (int mi = 0; mi < 2; mi++) {
            #pragma unroll
            for (int half = 0; half < 2; half++) {
                int r = m0 + wm * 32 + mi * 16 + half * 8 + group;
                if (r >= M) continue;
                float2 v;
                v.x = acc[mi][ni][half * 2 + 0] + b2.x;
                v.y = acc[mi][ni][half * 2 + 1] + b2.y;
                if (act) { v.x = gelu_t(v.x); v.y = gelu_t(v.y); }
                if (Cf) *(float2*)(Cf + (size_t)r * N + cc) = v;
                if (Ct) {
                    uint2 u; u.x = f2tf32(v.x); u.y = f2tf32(v.y);
                    *(uint2*)(Ct + (size_t)r * N + cc) = u;
                }
            }
        }
    }
}

// ---------------- attention kernel (fp32 compute, tf32 output) ----------------
__global__ void __launch_bounds__(256) attn_kernel(
    const float* __restrict__ img, const float* __restrict__ title,
    const int* __restrict__ mask,
    const float* __restrict__ scale_img, const float* __restrict__ scale_title,
    uint32_t* __restrict__ attn)
{
    int blk = blockIdx.x;
    int h  = blk % H_;
    int bl = blk / H_;

    const float* imgp = img   + (size_t)bl * P_ * D_ + h * DH_;
    const float* titp = title + (size_t)bl * T_ * D_ + h * DH_;
    const int*   mp   = mask  + bl * T_;

    __shared__ float s_img[P_][DH_ + 1];
    __shared__ float s_tit[T_][DH_ + 1];
    __shared__ float s_raw [P_][T_];
    __shared__ float s_pimg[P_][T_];
    __shared__ float s_ptit[T_][P_];
    __shared__ float s_mask[T_];

    int tid = threadIdx.x;

    for (int i = tid; i < P_ * DH_; i += 256) {
        int p = i / DH_, d = i % DH_;
        s_img[p][d] = imgp[(size_t)p * D_ + d];
    }
    for (int i = tid; i < T_ * DH_; i += 256) {
        int t = i / DH_, d = i % DH_;
        s_tit[t][d] = titp[(size_t)t * D_ + d];
    }
    if (tid < T_) s_mask[tid] = (float)mp[tid];
    __syncthreads();

    for (int i = tid; i < P_ * T_; i += 256) {
        int p = i / T_, t = i % T_;
        float acc = 0.f;
        #pragma unroll
        for (int d = 0; d < DH_; d++) acc += s_img[p][d] * s_tit[t][d];
        s_raw[p][t] = acc * 0.125f;
    }
    __syncthreads();

    if (tid < P_) {
        int p = tid;
        float sc = scale_img[h * P_ + p];
        float row[T_];
        float mx = -INFINITY;
        #pragma unroll
        for (int t = 0; t < T_; t++) {
            float v = (s_mask[t] != 0.f) ? s_raw[p][t] * sc : NEGV;
            row[t] = v;
            mx = fmaxf(mx, v);
        }
        float sum = 0.f;
        #pragma unroll
        for (int t = 0; t < T_; t++) { float e = expf(row[t] - mx); row[t] = e; sum += e; }
        float inv = 1.f / sum;
        #pragma unroll
        for (int t = 0; t < T_; t++) s_pimg[p][t] = row[t] * inv;
    }
    if (tid >= 64 && tid < 64 + T_) {
        int t = tid - 64;
        float sc = scale_title[h * T_ + t];
        bool dead = (s_mask[t] == 0.f);
        float mx = -INFINITY;
        for (int p = 0; p < P_; p++) {
            float v = dead ? NEGV : s_raw[p][t] * sc;
            mx = fmaxf(mx, v);
        }
        float sum = 0.f;
        for (int p = 0; p < P_; p++) {
            float v = dead ? NEGV : s_raw[p][t] * sc;
            float e = expf(v - mx);
            s_ptit[t][p] = e;
            sum += e;
        }
        float inv = 1.f / sum;
        for (int p = 0; p < P_; p++) s_ptit[t][p] *= inv;
    }
    __syncthreads();

    uint32_t* out_img = attn + (size_t)bl * T_ * D_ + h * DH_;
    for (int i = tid; i < T_ * DH_; i += 256) {
        int t = i / DH_, d = i % DH_;
        float acc = 0.f;
        #pragma unroll 7
        for (int p = 0; p < P_; p++) acc += s_ptit[t][p] * s_img[p][d];
        out_img[(size_t)t * D_ + d] = f2tf32(acc);
    }
    uint32_t* out_tit = attn + (size_t)IMG_TOK * D_ + (size_t)bl * P_ * D_ + h * DH_;
    for (int i = tid; i < P_ * DH_; i += 256) {
        int p = i / DH_, d = i % DH_;
        float acc = 0.f;
        #pragma unroll
        for (int t = 0; t < T_; t++) acc += s_pimg[p][t] * s_tit[t][d];
        out_tit[(size_t)p * D_ + d] = f2tf32(acc);
    }
}

// ---------------- residual + LayerNorm: 4 warps/block, one token per warp ----------------
__global__ void __launch_bounds__(128) ln_res_kernel(
    const float* __restrict__ hid, const float* __restrict__ ffn,
    const float* __restrict__ aimg, const float* __restrict__ bimg,
    const float* __restrict__ atit, const float* __restrict__ btit,
    float* __restrict__ out)
{
    int tok = blockIdx.x * 4 + (threadIdx.x >> 5);
    if (tok >= NTOK) return;
    const float* a  = (tok < IMG_TOK) ? aimg : atit;
    const float* bb = (tok < IMG_TOK) ? bimg : btit;
    const float* x  = ffn + (size_t)tok * D_;
    const float* hh = hid + (size_t)tok * D_;
    float* o        = out + (size_t)tok * D_;

    int lane = threadIdx.x & 31;
    float v[16];
    float s = 0.f;
    #pragma unroll
    for (int i = 0; i < 4; i++) {
        float4 t4 = *(const float4*)(x + lane * 4 + i * 128);
        v[i*4+0] = t4.x; v[i*4+1] = t4.y; v[i*4+2] = t4.z; v[i*4+3] = t4.w;
        s += t4.x + t4.y + t4.z + t4.w;
    }
    #pragma unroll
    for (int off = 16; off > 0; off >>= 1) s += __shfl_xor_sync(0xffffffffu, s, off);
    float mean = s * (1.f / 512.f);

    float sq = 0.f;
    #pragma unroll
    for (int i = 0; i < 16; i++) { float d = v[i] - mean; sq += d * d; }
    #pragma unroll
    for (int off = 16; off > 0; off >>= 1) sq += __shfl_xor_sync(0xffffffffu, sq, off);
    float stdv = sqrtf(sq * (1.f / 511.f));
    float inv = 1.f / (stdv + EPS_);

    #pragma unroll
    for (int i = 0; i < 4; i++) {
        int c0 = lane * 4 + i * 128;
        float4 a4 = *(const float4*)(a  + c0);
        float4 b4 = *(const float4*)(bb + c0);
        float4 h4 = *(const float4*)(hh + c0);
        float4 r;
        r.x = h4.x + a4.x * (v[i*4+0] - mean) * inv + b4.x;
        r.y = h4.y + a4.y * (v[i*4+1] - mean) * inv + b4.y;
        r.z = h4.z + a4.z * (v[i*4+2] - mean) * inv + b4.z;
        r.w = h4.w + a4.w * (v[i*4+3] - mean) * inv + b4.w;
        *(float4*)(o + c0) = r;
    }
}

// ---------------- launch ----------------
#define MTILES ((NTOK + 127) / 128)      // 432
#define SPLIT_TILE (IMG_TOK / 128)       // 125 (exact)

extern "C" void kernel_launch(void* const* d_in, const int* in_sizes, int n_in,
                              void* d_out, int out_size)
{
    const float* img         = (const float*)d_in[0];
    const float* title       = (const float*)d_in[1];
    const int*   mask        = (const int*)  d_in[2];
    const float* scale_img   = (const float*)d_in[3];
    const float* scale_title = (const float*)d_in[4];
    const float* w_proj      = (const float*)d_in[5];
    const float* b_proj      = (const float*)d_in[6];
    const float* w1_img      = (const float*)d_in[7];
    const float* b1_img      = (const float*)d_in[8];
    const float* w2_img      = (const float*)d_in[9];
    const float* b2_img      = (const float*)d_in[10];
    const float* w1_tit      = (const float*)d_in[11];
    const float* b1_tit      = (const float*)d_in[12];
    const float* w2_tit      = (const float*)d_in[13];
    const float* b2_tit      = (const float*)d_in[14];
    const float* ln_a_img    = (const float*)d_in[15];
    const float* ln_b_img    = (const float*)d_in[16];
    const float* ln_a_tit    = (const float*)d_in[17];
    const float* ln_b_tit    = (const float*)d_in[18];
    float* out = (float*)d_out;

    uint32_t *attn_t, *hid_t, *ffn1_t, *wbuf;
    float *hid, *ffn2;
    cudaGetSymbolAddress((void**)&attn_t, g_attn_t);
    cudaGetSymbolAddress((void**)&hid,    g_hid);
    cudaGetSymbolAddress((void**)&hid_t,  g_hid_t);
    cudaGetSymbolAddress((void**)&ffn1_t, g_ffn1_t);
    cudaGetSymbolAddress((void**)&ffn2,   g_ffn2);
    cudaGetSymbolAddress((void**)&wbuf,   g_wbuf);

    cudaFuncSetAttribute(mma_gemm, cudaFuncAttributeMaxDynamicSharedMemorySize, MM_SMEM);

    // 0) weights -> tf32 bits
    prep_w<<<(WTOTAL / 4 + 255) / 256, 256>>>(w_proj, w1_img, w1_tit, w2_img, w2_tit, wbuf);

    // 1) attention (writes tf32)
    attn_kernel<<<B_ * L_ * H_, 256>>>(img, title, mask, scale_img, scale_title, attn_t);

    // 2) shared projection: fp32 hid (residual) + tf32 hid_t (FFN1 input)
    mma_gemm<<<dim3(D_ / 128, MTILES), 256, MM_SMEM>>>(
        attn_t, wbuf + WOFF_PROJ, b_proj, wbuf + WOFF_PROJ, b_proj, MTILES,
        hid, hid_t, NTOK, D_, D_, 0);

    // 3) FFN1 (+GELU), both branches, tf32 output only
    mma_gemm<<<dim3(DFF_ / 128, MTILES), 256, MM_SMEM>>>(
        hid_t, wbuf + WOFF_W1I, b1_img, wbuf + WOFF_W1T, b1_tit, SPLIT_TILE,
        (float*)nullptr, ffn1_t, NTOK, DFF_, D_, 1);

    // 4) FFN2, both branches, fp32 output only
    mma_gemm<<<dim3(D_ / 128, MTILES), 256, MM_SMEM>>>(
        ffn1_t, wbuf + WOFF_W2I, b2_img, wbuf + WOFF_W2T, b2_tit, SPLIT_TILE,
        ffn2, (uint32_t*)nullptr, NTOK, D_, DFF_, 0);

    // 5) out = hid + LN(ffn2)
    ln_res_kernel<<<(NTOK + 3) / 4, 128>>>(hid, ffn2, ln_a_img, ln_b_img,
                                           ln_a_tit, ln_b_tit, out);
}

// round 9
// speedup vs baseline: 1.2612x; 1.2612x over previous
#include <cuda_runtime.h>
#include <math.h>
#include <stdint.h>

// Problem constants
#define B_   16
#define L_   50
#define P_   49
#define T_   20
#define D_   512
#define H_   8
#define DH_  64
#define DFF_ 2048
#define IMG_TOK (B_*L_*T_)   // 16000  (= 125 tiles of 128, exactly)
#define TIT_TOK (B_*L_*P_)   // 39200
#define NTOK (IMG_TOK + TIT_TOK)  // 55200
#define NEGV (-1000000000.0f)
#define EPS_ 1e-6f

// ---------------- scratch ----------------
__device__ uint32_t g_attn_t[NTOK * D_];              // attention out, tf32 bits
__device__ float    g_hid   [NTOK * D_];              // proj out fp32 (residual)
__device__ uint32_t g_hid_t [NTOK * D_];              // proj out tf32 (FFN1 input)
__device__ uint32_t g_ffn1_t[(size_t)NTOK * DFF_];    // gelu out tf32 (FFN2 input)
__device__ float    g_ffn2  [NTOK * D_];              // FFN2 out fp32 (LN input)

// pre-converted weights (tf32 bits), packed segments
#define WOFF_PROJ 0
#define WOFF_W1I  (512*512)
#define WOFF_W1T  (WOFF_W1I + 2048*512)
#define WOFF_W2I  (WOFF_W1T + 2048*512)
#define WOFF_W2T  (WOFF_W2I + 512*2048)
#define WTOTAL    (WOFF_W2T + 512*2048)   // 4456448
__device__ uint32_t g_wbuf[WTOTAL];

__device__ __forceinline__ uint32_t f2tf32(float f) {
    uint32_t r; asm("cvt.rna.tf32.f32 %0, %1;" : "=r"(r) : "f"(f)); return r;
}
// gelu_tanh(x) = 0.5 x (1 + tanh(u)) = x * sigmoid(2u),  u = sqrt(2/pi)(x + 0.044715 x^3)
__device__ __forceinline__ float gelu_t(float x) {
    float x3 = x * x * x;
    float u = 0.7978845608028654f * (x + 0.044715f * x3);
    return __fdividef(x, 1.f + __expf(-2.f * u));
}
__device__ __forceinline__ void mma_tf32(float* c, const uint32_t* a, const uint32_t* b) {
    asm volatile(
        "mma.sync.aligned.m16n8k8.row.col.f32.tf32.tf32.f32 "
        "{%0,%1,%2,%3}, {%4,%5,%6,%7}, {%8,%9}, {%0,%1,%2,%3};"
        : "+f"(c[0]), "+f"(c[1]), "+f"(c[2]), "+f"(c[3])
        : "r"(a[0]), "r"(a[1]), "r"(a[2]), "r"(a[3]), "r"(b[0]), "r"(b[1]));
}
__device__ __forceinline__ void cp_async16(uint32_t dst, const void* src, uint32_t nbytes) {
    asm volatile("cp.async.cg.shared.global [%0], [%1], 16, %2;"
                 :: "r"(dst), "l"(src), "r"(nbytes));
}
__device__ __forceinline__ void cp_commit() {
    asm volatile("cp.async.commit_group;" ::: "memory");
}
template <int N>
__device__ __forceinline__ void cp_wait() {
    asm volatile("cp.async.wait_group %0;" :: "n"(N) : "memory");
}

// ---------------- weight pre-conversion (fp32 -> tf32 bits) ----------------
__global__ void __launch_bounds__(256) prep_w(
    const float* __restrict__ a0, const float* __restrict__ a1,
    const float* __restrict__ a2, const float* __restrict__ a3,
    const float* __restrict__ a4, uint32_t* __restrict__ o)
{
    size_t i = ((size_t)blockIdx.x * 256 + threadIdx.x) * 4;
    if (i >= WTOTAL) return;
    const float* src; size_t off;
    if      (i < WOFF_W1I) { src = a0; off = i; }
    else if (i < WOFF_W1T) { src = a1; off = i - WOFF_W1I; }
    else if (i < WOFF_W2I) { src = a2; off = i - WOFF_W1T; }
    else if (i < WOFF_W2T) { src = a3; off = i - WOFF_W2I; }
    else                   { src = a4; off = i - WOFF_W2T; }
    float4 v = *(const float4*)(src + off);
    uint4 u; u.x = f2tf32(v.x); u.y = f2tf32(v.y); u.z = f2tf32(v.z); u.w = f2tf32(v.w);
    *(uint4*)(o + i) = u;
}

// ---------------- tensor-core GEMM via mma.sync tf32 + 2-stage cp.async ----------------
// Operands are pre-converted tf32 bit patterns: NO cvt in the mainloop.
// C = A[M,K] @ Wsel[N,K]^T + bias (+GELU). Mainloop unrolled by 2: all stage
// indices are literals (no dynamic register-array indexing).
#define SROW 36                       // smem row stride (u32); row = 144 B, conflict-free
#define TILE_BYTES (128 * SROW * 4)   // 18432 B per matrix per buffer
#define MM_SMEM (4 * TILE_BYTES)      // 73728 B

__global__ void __launch_bounds__(256, 2) mma_gemm(
    const uint32_t* __restrict__ A,
    const uint32_t* __restrict__ W0, const float* __restrict__ b0,
    const uint32_t* __restrict__ W1, const float* __restrict__ b1,
    int split_tile,
    float* __restrict__ Cf, uint32_t* __restrict__ Ct,
    int M, int N, int K, int act)
{
    extern __shared__ uint32_t sh[];
    const uint32_t sm_base = (uint32_t)__cvta_generic_to_shared(sh);
    const uint32_t aU0 = sm_base;
    const uint32_t aU1 = sm_base + TILE_BYTES;
    const uint32_t bU0 = sm_base + 2 * TILE_BYTES;
    const uint32_t bU1 = sm_base + 3 * TILE_BYTES;
    const uint32_t* aF0 = sh;
    const uint32_t* aF1 = sh + TILE_BYTES / 4;
    const uint32_t* bF0 = sh + 2 * (TILE_BYTES / 4);
    const uint32_t* bF1 = sh + 3 * (TILE_BYTES / 4);

    const int tid = threadIdx.x;
    const int m0 = blockIdx.y * 128, n0 = blockIdx.x * 128;
    const uint32_t* W  = (blockIdx.y < split_tile) ? W0 : W1;
    const float* bias  = (blockIdx.y < split_tile) ? b0 : b1;

    const int w = tid >> 5, lane = tid & 31;
    const int wm = w & 3, wn = w >> 2;          // warp tile: rows wm*32, cols wn*64
    const int group = lane >> 2, quad = lane & 3;

    const int lrow0 = tid >> 3;        // copy mapping: rows lrow0 + t*32
    const int lc4   = tid & 7;         // 16B column

    float acc[2][8][4];
    #pragma unroll
    for (int i = 0; i < 2; i++)
        #pragma unroll
        for (int j = 0; j < 8; j++)
            #pragma unroll
            for (int q = 0; q < 4; q++) acc[i][j][q] = 0.f;

    const int nch = K >> 5;            // always even (16 or 64)

    auto issue = [&](uint32_t aU, uint32_t bU, int kc) {
        #pragma unroll
        for (int t = 0; t < 4; t++) {
            int row = lrow0 + t * 32;
            uint32_t off = (uint32_t)(row * 144 + lc4 * 16);
            size_t arow = (m0 + row < M) ? (size_t)(m0 + row) : 0;
            cp_async16(aU + off, A + arow * K + kc + lc4 * 4,
                       (m0 + row < M) ? 16u : 0u);
            cp_async16(bU + off, W + (size_t)(n0 + row) * K + kc + lc4 * 4, 16u);
        }
        cp_commit();
    };

    auto compute = [&](const uint32_t* ap, const uint32_t* bp) {
        #pragma unroll
        for (int ks = 0; ks < 4; ks++) {
            const int k0 = ks * 8;
            uint32_t afr[2][4];
            #pragma unroll
            for (int mi = 0; mi < 2; mi++) {
                int r = wm * 32 + mi * 16 + group;
                afr[mi][0] = ap[(r    ) * SROW + k0 + quad];
                afr[mi][1] = ap[(r + 8) * SROW + k0 + quad];
                afr[mi][2] = ap[(r    ) * SROW + k0 + quad + 4];
                afr[mi][3] = ap[(r + 8) * SROW + k0 + quad + 4];
            }
            uint32_t bfr[8][2];
            #pragma unroll
            for (int ni = 0; ni < 8; ni++) {
                int n = wn * 64 + ni * 8 + group;
                bfr[ni][0] = bp[n * SROW + k0 + quad];
                bfr[ni][1] = bp[n * SROW + k0 + quad + 4];
            }
            #pragma unroll
            for (int mi = 0; mi < 2; mi++)
                #pragma unroll
                for (int ni = 0; ni < 8; ni++)
                    mma_tf32(acc[mi][ni], afr[mi], bfr[ni]);
        }
    };

    // prologue
    issue(aU0, bU0, 0);

    // mainloop: unrolled by 2, literal stage indices, R6-proven schedule
    for (int c = 0; c < nch; c += 2) {
        // chunk c (buffer 0)
        issue(aU1, bU1, (c + 1) << 5);       // c+1 < nch always (nch even)
        cp_wait<1>();
        __syncthreads();
        compute(aF0, bF0);
        __syncthreads();
        // chunk c+1 (buffer 1)
        if (c + 2 < nch) {
            issue(aU0, bU0, (c + 2) << 5);
            cp_wait<1>();
        } else {
            cp_wait<0>();
        }
        __syncthreads();
        compute(aF1, bF1);
        __syncthreads();
    }

    // epilogue: bias + optional GELU; fp32 and/or tf32 outputs
    #pragma unroll
    for (int ni = 0; ni < 8; ni++) {
        int cc = n0 + wn * 64 + ni * 8 + quad * 2;
        float2 b2 = *(const float2*)(bias + cc);
        #pragma unroll
        for (int mi = 0; mi < 2; mi++) {
            #pragma unroll
            for (int half = 0; half < 2; half++) {
                int r = m0 + wm * 32 + mi * 16 + half * 8 + group;
                if (r >= M) continue;
                float2 v;
                v.x = acc[mi][ni][half * 2 + 0] + b2.x;
                v.y = acc[mi][ni][half * 2 + 1] + b2.y;
                if (act) { v.x = gelu_t(v.x); v.y = gelu_t(v.y); }
                if (Cf) *(float2*)(Cf + (size_t)r * N + cc) = v;
                if (Ct) {
                    uint2 u; u.x = f2tf32(v.x); u.y = f2tf32(v.y);
                    *(uint2*)(Ct + (size_t)r * N + cc) = u;
                }
            }
        }
    }
}

// ---------------- attention kernel (fp32 compute, tf32 output) ----------------
__global__ void __launch_bounds__(256) attn_kernel(
    const float* __restrict__ img, const float* __restrict__ title,
    const int* __restrict__ mask,
    const float* __restrict__ scale_img, const float* __restrict__ scale_title,
    uint32_t* __restrict__ attn)
{
    int blk = blockIdx.x;
    int h  = blk % H_;
    int bl = blk / H_;

    const float* imgp = img   + (size_t)bl * P_ * D_ + h * DH_;
    const float* titp = title + (size_t)bl * T_ * D_ + h * DH_;
    const int*   mp   = mask  + bl * T_;

    __shared__ float s_img[P_][DH_ + 1];
    __shared__ float s_tit[T_][DH_ + 1];
    __shared__ float s_raw [P_][T_];
    __shared__ float s_pimg[P_][T_];
    __shared__ float s_ptit[T_][P_];
    __shared__ float s_mask[T_];

    int tid = threadIdx.x;

    for (int i = tid; i < P_ * DH_; i += 256) {
        int p = i / DH_, d = i % DH_;
        s_img[p][d] = imgp[(size_t)p * D_ + d];
    }
    for (int i = tid; i < T_ * DH_; i += 256) {
        int t = i / DH_, d = i % DH_;
        s_tit[t][d] = titp[(size_t)t * D_ + d];
    }
    if (tid < T_) s_mask[tid] = (float)mp[tid];
    __syncthreads();

    for (int i = tid; i < P_ * T_; i += 256) {
        int p = i / T_, t = i % T_;
        float acc = 0.f;
        #pragma unroll
        for (int d = 0; d < DH_; d++) acc += s_img[p][d] * s_tit[t][d];
        s_raw[p][t] = acc * 0.125f;
    }
    __syncthreads();

    if (tid < P_) {
        int p = tid;
        float sc = scale_img[h * P_ + p];
        float row[T_];
        float mx = -INFINITY;
        #pragma unroll
        for (int t = 0; t < T_; t++) {
            float v = (s_mask[t] != 0.f) ? s_raw[p][t] * sc : NEGV;
            row[t] = v;
            mx = fmaxf(mx, v);
        }
        float sum = 0.f;
        #pragma unroll
        for (int t = 0; t < T_; t++) { float e = __expf(row[t] - mx); row[t] = e; sum += e; }
        float inv = 1.f / sum;
        #pragma unroll
        for (int t = 0; t < T_; t++) s_pimg[p][t] = row[t] * inv;
    }
    if (tid >= 64 && tid < 64 + T_) {
        int t = tid - 64;
        float sc = scale_title[h * T_ + t];
        bool dead = (s_mask[t] == 0.f);
        float mx = -INFINITY;
        for (int p = 0; p < P_; p++) {
            float v = dead ? NEGV : s_raw[p][t] * sc;
            mx = fmaxf(mx, v);
        }
        float sum = 0.f;
        for (int p = 0; p < P_; p++) {
            float v = dead ? NEGV : s_raw[p][t] * sc;
            float e = __expf(v - mx);
            s_ptit[t][p] = e;
            sum += e;
        }
        float inv = 1.f / sum;
        for (int p = 0; p < P_; p++) s_ptit[t][p] *= inv;
    }
    __syncthreads();

    uint32_t* out_img = attn + (size_t)bl * T_ * D_ + h * DH_;
    for (int i = tid; i < T_ * DH_; i += 256) {
        int t = i / DH_, d = i % DH_;
        float acc = 0.f;
        #pragma unroll 7
        for (int p = 0; p < P_; p++) acc += s_ptit[t][p] * s_img[p][d];
        out_img[(size_t)t * D_ + d] = f2tf32(acc);
    }
    uint32_t* out_tit = attn + (size_t)IMG_TOK * D_ + (size_t)bl * P_ * D_ + h * DH_;
    for (int i = tid; i < P_ * DH_; i += 256) {
        int p = i / DH_, d = i % DH_;
        float acc = 0.f;
        #pragma unroll
        for (int t = 0; t < T_; t++) acc += s_pimg[p][t] * s_tit[t][d];
        out_tit[(size_t)p * D_ + d] = f2tf32(acc);
    }
}

// ---------------- residual + LayerNorm: 4 warps/block, one token per warp ----------------
__global__ void __launch_bounds__(128) ln_res_kernel(
    const float* __restrict__ hid, const float* __restrict__ ffn,
    const float* __restrict__ aimg, const float* __restrict__ bimg,
    const float* __restrict__ atit, const float* __restrict__ btit,
    float* __restrict__ out)
{
    int tok = blockIdx.x * 4 + (threadIdx.x >> 5);
    if (tok >= NTOK) return;
    const float* a  = (tok < IMG_TOK) ? aimg : atit;
    const float* bb = (tok < IMG_TOK) ? bimg : btit;
    const float* x  = ffn + (size_t)tok * D_;
    const float* hh = hid + (size_t)tok * D_;
    float* o        = out + (size_t)tok * D_;

    int lane = threadIdx.x & 31;
    float v[16];
    float s = 0.f;
    #pragma unroll
    for (int i = 0; i < 4; i++) {
        float4 t4 = *(const float4*)(x + lane * 4 + i * 128);
        v[i*4+0] = t4.x; v[i*4+1] = t4.y; v[i*4+2] = t4.z; v[i*4+3] = t4.w;
        s += t4.x + t4.y + t4.z + t4.w;
    }
    #pragma unroll
    for (int off = 16; off > 0; off >>= 1) s += __shfl_xor_sync(0xffffffffu, s, off);
    float mean = s * (1.f / 512.f);

    float sq = 0.f;
    #pragma unroll
    for (int i = 0; i < 16; i++) { float d = v[i] - mean; sq += d * d; }
    #pragma unroll
    for (int off = 16; off > 0; off >>= 1) sq += __shfl_xor_sync(0xffffffffu, sq, off);
    float stdv = sqrtf(sq * (1.f / 511.f));
    float inv = 1.f / (stdv + EPS_);

    #pragma unroll
    for (int i = 0; i < 4; i++) {
        int c0 = lane * 4 + i * 128;
        float4 a4 = *(const float4*)(a  + c0);
        float4 b4 = *(const float4*)(bb + c0);
        float4 h4 = *(const float4*)(hh + c0);
        float4 r;
        r.x = h4.x + a4.x * (v[i*4+0] - mean) * inv + b4.x;
        r.y = h4.y + a4.y * (v[i*4+1] - mean) * inv + b4.y;
        r.z = h4.z + a4.z * (v[i*4+2] - mean) * inv + b4.z;
        r.w = h4.w + a4.w * (v[i*4+3] - mean) * inv + b4.w;
        *(float4*)(o + c0) = r;
    }
}

// ---------------- launch ----------------
#define MTILES ((NTOK + 127) / 128)      // 432
#define SPLIT_TILE (IMG_TOK / 128)       // 125 (exact)

extern "C" void kernel_launch(void* const* d_in, const int* in_sizes, int n_in,
                              void* d_out, int out_size)
{
    const float* img         = (const float*)d_in[0];
    const float* title       = (const float*)d_in[1];
    const int*   mask        = (const int*)  d_in[2];
    const float* scale_img   = (const float*)d_in[3];
    const float* scale_title = (const float*)d_in[4];
    const float* w_proj      = (const float*)d_in[5];
    const float* b_proj      = (const float*)d_in[6];
    const float* w1_img      = (const float*)d_in[7];
    const float* b1_img      = (const float*)d_in[8];
    const float* w2_img      = (const float*)d_in[9];
    const float* b2_img      = (const float*)d_in[10];
    const float* w1_tit      = (const float*)d_in[11];
    const float* b1_tit      = (const float*)d_in[12];
    const float* w2_tit      = (const float*)d_in[13];
    const float* b2_tit      = (const float*)d_in[14];
    const float* ln_a_img    = (const float*)d_in[15];
    const float* ln_b_img    = (const float*)d_in[16];
    const float* ln_a_tit    = (const float*)d_in[17];
    const float* ln_b_tit    = (const float*)d_in[18];
    float* out = (float*)d_out;

    uint32_t *attn_t, *hid_t, *ffn1_t, *wbuf;
    float *hid, *ffn2;
    cudaGetSymbolAddress((void**)&attn_t, g_attn_t);
    cudaGetSymbolAddress((void**)&hid,    g_hid);
    cudaGetSymbolAddress((void**)&hid_t,  g_hid_t);
    cudaGetSymbolAddress((void**)&ffn1_t, g_ffn1_t);
    cudaGetSymbolAddress((void**)&ffn2,   g_ffn2);
    cudaGetSymbolAddress((void**)&wbuf,   g_wbuf);

    cudaFuncSetAttribute(mma_gemm, cudaFuncAttributeMaxDynamicSharedMemorySize, MM_SMEM);

    // 0) weights -> tf32 bits
    prep_w<<<(WTOTAL / 4 + 255) / 256, 256>>>(w_proj, w1_img, w1_tit, w2_img, w2_tit, wbuf);

    // 1) attention (writes tf32)
    attn_kernel<<<B_ * L_ * H_, 256>>>(img, title, mask, scale_img, scale_title, attn_t);

    // 2) shared projection: fp32 hid (residual) + tf32 hid_t (FFN1 input)
    mma_gemm<<<dim3(D_ / 128, MTILES), 256, MM_SMEM>>>(
        attn_t, wbuf + WOFF_PROJ, b_proj, wbuf + WOFF_PROJ, b_proj, MTILES,
        hid, hid_t, NTOK, D_, D_, 0);

    // 3) FFN1 (+GELU), both branches, tf32 output only
    mma_gemm<<<dim3(DFF_ / 128, MTILES), 256, MM_SMEM>>>(
        hid_t, wbuf + WOFF_W1I, b1_img, wbuf + WOFF_W1T, b1_tit, SPLIT_TILE,
        (float*)nullptr, ffn1_t, NTOK, DFF_, D_, 1);

    // 4) FFN2, both branches, fp32 output only
    mma_gemm<<<dim3(D_ / 128, MTILES), 256, MM_SMEM>>>(
        ffn1_t, wbuf + WOFF_W2I, b2_img, wbuf + WOFF_W2T, b2_tit, SPLIT_TILE,
        ffn2, (uint32_t*)nullptr, NTOK, D_, DFF_, 0);

    // 5) out = hid + LN(ffn2)
    ln_res_kernel<<<(NTOK + 3) / 4, 128>>>(hid, ffn2, ln_a_img, ln_b_img,
                                           ln_a_tit, ln_b_tit, out);
}

// round 12
// speedup vs baseline: 1.3725x; 1.0882x over previous
#include <cuda_runtime.h>
#include <math.h>
#include <stdint.h>

// Problem constants
#define B_   16
#define L_   50
#define P_   49
#define T_   20
#define D_   512
#define H_   8
#define DH_  64
#define DFF_ 2048
#define IMG_TOK (B_*L_*T_)   // 16000  (= 125 tiles of 128, exactly)
#define TIT_TOK (B_*L_*P_)   // 39200
#define NTOK (IMG_TOK + TIT_TOK)  // 55200
#define NEGV (-1000000000.0f)
#define EPS_ 1e-6f

// ---------------- scratch ----------------
__device__ uint32_t g_attn_t[NTOK * D_];              // attention out, tf32 bits
__device__ float    g_hid   [NTOK * D_];              // proj out fp32 (residual)
__device__ uint32_t g_hid_t [NTOK * D_];              // proj out tf32 (FFN1 input)
__device__ uint32_t g_ffn1_t[(size_t)NTOK * DFF_];    // gelu out tf32 (FFN2 input)
__device__ float    g_ffn2  [NTOK * D_];              // FFN2 out fp32 (LN input)

// pre-converted weights (tf32 bits), packed segments
#define WOFF_PROJ 0
#define WOFF_W1I  (512*512)
#define WOFF_W1T  (WOFF_W1I + 2048*512)
#define WOFF_W2I  (WOFF_W1T + 2048*512)
#define WOFF_W2T  (WOFF_W2I + 512*2048)
#define WTOTAL    (WOFF_W2T + 512*2048)   // 4456448
__device__ uint32_t g_wbuf[WTOTAL];

__device__ __forceinline__ uint32_t f2tf32(float f) {
    uint32_t r; asm("cvt.rna.tf32.f32 %0, %1;" : "=r"(r) : "f"(f)); return r;
}
// gelu_tanh(x) = 0.5 x (1 + tanh(u)) = x * sigmoid(2u),  u = sqrt(2/pi)(x + 0.044715 x^3)
__device__ __forceinline__ float gelu_t(float x) {
    float x3 = x * x * x;
    float u = 0.7978845608028654f * (x + 0.044715f * x3);
    return __fdividef(x, 1.f + __expf(-2.f * u));
}
__device__ __forceinline__ void mma_tf32(float* c, const uint32_t* a, const uint32_t* b) {
    asm volatile(
        "mma.sync.aligned.m16n8k8.row.col.f32.tf32.tf32.f32 "
        "{%0,%1,%2,%3}, {%4,%5,%6,%7}, {%8,%9}, {%0,%1,%2,%3};"
        : "+f"(c[0]), "+f"(c[1]), "+f"(c[2]), "+f"(c[3])
        : "r"(a[0]), "r"(a[1]), "r"(a[2]), "r"(a[3]), "r"(b[0]), "r"(b[1]));
}
__device__ __forceinline__ void ldsm4(uint32_t& r0, uint32_t& r1, uint32_t& r2, uint32_t& r3,
                                      uint32_t addr) {
    asm volatile("ldmatrix.sync.aligned.m8n8.x4.shared.b16 {%0,%1,%2,%3}, [%4];"
                 : "=r"(r0), "=r"(r1), "=r"(r2), "=r"(r3) : "r"(addr));
}
__device__ __forceinline__ void cp_async16(uint32_t dst, const void* src, uint32_t nbytes) {
    asm volatile("cp.async.cg.shared.global [%0], [%1], 16, %2;"
                 :: "r"(dst), "l"(src), "r"(nbytes));
}
__device__ __forceinline__ void cp_commit() {
    asm volatile("cp.async.commit_group;" ::: "memory");
}
template <int N>
__device__ __forceinline__ void cp_wait() {
    asm volatile("cp.async.wait_group %0;" :: "n"(N) : "memory");
}

// ---------------- weight pre-conversion (fp32 -> tf32 bits) ----------------
__global__ void __launch_bounds__(256) prep_w(
    const float* __restrict__ a0, const float* __restrict__ a1,
    const float* __restrict__ a2, const float* __restrict__ a3,
    const float* __restrict__ a4, uint32_t* __restrict__ o)
{
    size_t i = ((size_t)blockIdx.x * 256 + threadIdx.x) * 4;
    if (i >= WTOTAL) return;
    const float* src; size_t off;
    if      (i < WOFF_W1I) { src = a0; off = i; }
    else if (i < WOFF_W1T) { src = a1; off = i - WOFF_W1I; }
    else if (i < WOFF_W2I) { src = a2; off = i - WOFF_W1T; }
    else if (i < WOFF_W2T) { src = a3; off = i - WOFF_W2I; }
    else                   { src = a4; off = i - WOFF_W2T; }
    float4 v = *(const float4*)(src + off);
    uint4 u; u.x = f2tf32(v.x); u.y = f2tf32(v.y); u.z = f2tf32(v.z); u.w = f2tf32(v.w);
    *(uint4*)(o + i) = u;
}

// ---------------- tensor-core GEMM via mma.sync tf32 + 2-stage cp.async ----------------
// Operands are pre-converted tf32 bit patterns. Fragment loads via ldmatrix.x4
// (8x8 tf32 tile == 8 rows x 16B == ldmatrix b16 row format; register
// distribution thread(4g+tg) <- element(g,tg) matches the mma fragment layout).
#define SROW 36                       // smem row stride (u32); row = 144 B
#define TILE_BYTES (128 * SROW * 4)   // 18432 B per matrix per buffer
#define MM_SMEM (4 * TILE_BYTES)      // 73728 B

__global__ void __launch_bounds__(256, 2) mma_gemm(
    const uint32_t* __restrict__ A,
    const uint32_t* __restrict__ W0, const float* __restrict__ b0,
    const uint32_t* __restrict__ W1, const float* __restrict__ b1,
    int split_tile,
    float* __restrict__ Cf, uint32_t* __restrict__ Ct,
    int M, int N, int K, int act)
{
    extern __shared__ uint32_t sh[];
    const uint32_t sm_base = (uint32_t)__cvta_generic_to_shared(sh);
    const uint32_t aU0 = sm_base;
    const uint32_t aU1 = sm_base + TILE_BYTES;
    const uint32_t bU0 = sm_base + 2 * TILE_BYTES;
    const uint32_t bU1 = sm_base + 3 * TILE_BYTES;

    const int tid = threadIdx.x;
    const int m0 = blockIdx.y * 128, n0 = blockIdx.x * 128;
    const uint32_t* W  = (blockIdx.y < split_tile) ? W0 : W1;
    const float* bias  = (blockIdx.y < split_tile) ? b0 : b1;

    const int w = tid >> 5, lane = tid & 31;
    const int wm = w & 3, wn = w >> 2;          // warp tile: rows wm*32, cols wn*64
    const int group = lane >> 2, quad = lane & 3;

    const int lrow0 = tid >> 3;        // copy mapping: rows lrow0 + t*32
    const int lc4   = tid & 7;         // 16B column

    // ldmatrix per-thread byte offsets within a tile
    // A mats per mi: [rows 0-7 | k0..k0+3], [rows 8-15 | k0..], [rows 0-7 | k0+4..], [rows 8-15 | k0+4..]
    const uint32_t aOff = (uint32_t)((wm * 32 + (lane & 15)) * 144 + ((lane >> 4) << 4));
    // B mats per ni-pair: [n 0-7 | k0..], [n 0-7 | k0+4..], [n 8-15 | k0..], [n 8-15 | k0+4..]
    const uint32_t bOff = (uint32_t)((wn * 64 + (lane & 7) + ((lane >> 4) << 3)) * 144
                                     + (((lane >> 3) & 1) << 4));

    float acc[2][8][4];
    #pragma unroll
    for (int i = 0; i < 2; i++)
        #pragma unroll
        for (int j = 0; j < 8; j++)
            #pragma unroll
            for (int q = 0; q < 4; q++) acc[i][j][q] = 0.f;

    const int nch = K >> 5;            // always even (16 or 64)

    auto issue = [&](uint32_t aU, uint32_t bU, int kc) {
        #pragma unroll
        for (int t = 0; t < 4; t++) {
            int row = lrow0 + t * 32;
            uint32_t off = (uint32_t)(row * 144 + lc4 * 16);
            size_t arow = (m0 + row < M) ? (size_t)(m0 + row) : 0;
            cp_async16(aU + off, A + arow * K + kc + lc4 * 4,
                       (m0 + row < M) ? 16u : 0u);
            cp_async16(bU + off, W + (size_t)(n0 + row) * K + kc + lc4 * 4, 16u);
        }
        cp_commit();
    };

    auto compute = [&](uint32_t aT, uint32_t bT) {
        const uint32_t aA = aT + aOff;
        const uint32_t bA = bT + bOff;
        #pragma unroll
        for (int ks = 0; ks < 4; ks++) {
            const uint32_t k0b = ks * 32;          // 8 tf32 = 32 B per k-step
            uint32_t afr[2][4];
            ldsm4(afr[0][0], afr[0][1], afr[0][2], afr[0][3], aA + k0b);
            ldsm4(afr[1][0], afr[1][1], afr[1][2], afr[1][3], aA + 2304 + k0b);  // +16 rows
            uint32_t bfr[8][2];
            #pragma unroll
            for (int nn = 0; nn < 4; nn++)
                ldsm4(bfr[2*nn][0], bfr[2*nn][1], bfr[2*nn+1][0], bfr[2*nn+1][1],
                      bA + (uint32_t)nn * 2304 + k0b);                           // +16 n-rows
            #pragma unroll
            for (int mi = 0; mi < 2; mi++)
                #pragma unroll
                for (int ni = 0; ni < 8; ni++)
                    mma_tf32(acc[mi][ni], afr[mi], bfr[ni]);
        }
    };

    // prologue
    issue(aU0, bU0, 0);

    // mainloop: unrolled by 2, literal stage addresses, R6/R9-proven schedule
    for (int c = 0; c < nch; c += 2) {
        issue(aU1, bU1, (c + 1) << 5);       // c+1 < nch always (nch even)
        cp_wait<1>();
        __syncthreads();
        compute(aU0, bU0);
        __syncthreads();
        if (c + 2 < nch) {
            issue(aU0, bU0, (c + 2) << 5);
            cp_wait<1>();
        } else {
            cp_wait<0>();
        }
        __syncthreads();
        compute(aU1, bU1);
        __syncthreads();
    }

    // epilogue: bias + optional GELU; fp32 and/or tf32 outputs
    #pragma unroll
    for (int ni = 0; ni < 8; ni++) {
        int cc = n0 + wn * 64 + ni * 8 + quad * 2;
        float2 b2 = *(const float2*)(bias + cc);
        #pragma unroll
        for (int mi = 0; mi < 2; mi++) {
            #pragma unroll
            for (int half = 0; half < 2; half++) {
                int r = m0 + wm * 32 + mi * 16 + half * 8 + group;
                if (r >= M) continue;
                float2 v;
                v.x = acc[mi][ni][half * 2 + 0] + b2.x;
                v.y = acc[mi][ni][half * 2 + 1] + b2.y;
                if (act) { v.x = gelu_t(v.x); v.y = gelu_t(v.y); }
                if (Cf) *(float2*)(Cf + (size_t)r * N + cc) = v;
                if (Ct) {
                    uint2 u; u.x = f2tf32(v.x); u.y = f2tf32(v.y);
                    *(uint2*)(Ct + (size_t)r * N + cc) = u;
                }
            }
        }
    }
}

// ---------------- attention kernel (fp32 compute, tf32 output) ----------------
__global__ void __launch_bounds__(256) attn_kernel(
    const float* __restrict__ img, const float* __restrict__ title,
    const int* __restrict__ mask,
    const float* __restrict__ scale_img, const float* __restrict__ scale_title,
    uint32_t* __restrict__ attn)
{
    int blk = blockIdx.x;
    int h  = blk % H_;
    int bl = blk / H_;

    const float* imgp = img   + (size_t)bl * P_ * D_ + h * DH_;
    const float* titp = title + (size_t)bl * T_ * D_ + h * DH_;
    const int*   mp   = mask  + bl * T_;

    __shared__ float s_img[P_][DH_ + 1];
    __shared__ float s_tit[T_][DH_ + 1];
    __shared__ float s_raw [P_][T_];
    __shared__ float s_pimg[P_][T_];
    __shared__ float s_ptit[T_][P_];
    __shared__ float s_mask[T_];

    int tid = threadIdx.x;

    for (int i = tid; i < P_ * DH_; i += 256) {
        int p = i / DH_, d = i % DH_;
        s_img[p][d] = imgp[(size_t)p * D_ + d];
    }
    for (int i = tid; i < T_ * DH_; i += 256) {
        int t = i / DH_, d = i % DH_;
        s_tit[t][d] = titp[(size_t)t * D_ + d];
    }
    if (tid < T_) s_mask[tid] = (float)mp[tid];
    __syncthreads();

    for (int i = tid; i < P_ * T_; i += 256) {
        int p = i / T_, t = i % T_;
        float acc = 0.f;
        #pragma unroll
        for (int d = 0; d < DH_; d++) acc += s_img[p][d] * s_tit[t][d];
        s_raw[p][t] = acc * 0.125f;
    }
    __syncthreads();

    if (tid < P_) {
        int p = tid;
        float sc = scale_img[h * P_ + p];
        float row[T_];
        float mx = -INFINITY;
        #pragma unroll
        for (int t = 0; t < T_; t++) {
            float v = (s_mask[t] != 0.f) ? s_raw[p][t] * sc : NEGV;
            row[t] = v;
            mx = fmaxf(mx, v);
        }
        float sum = 0.f;
        #pragma unroll
        for (int t = 0; t < T_; t++) { float e = __expf(row[t] - mx); row[t] = e; sum += e; }
        float inv = 1.f / sum;
        #pragma unroll
        for (int t = 0; t < T_; t++) s_pimg[p][t] = row[t] * inv;
    }
    if (tid >= 64 && tid < 64 + T_) {
        int t = tid - 64;
        float sc = scale_title[h * T_ + t];
        bool dead = (s_mask[t] == 0.f);
        float mx = -INFINITY;
        for (int p = 0; p < P_; p++) {
            float v = dead ? NEGV : s_raw[p][t] * sc;
            mx = fmaxf(mx, v);
        }
        float sum = 0.f;
        for (int p = 0; p < P_; p++) {
            float v = dead ? NEGV : s_raw[p][t] * sc;
            float e = __expf(v - mx);
            s_ptit[t][p] = e;
            sum += e;
        }
        float inv = 1.f / sum;
        for (int p = 0; p < P_; p++) s_ptit[t][p] *= inv;
    }
    __syncthreads();

    uint32_t* out_img = attn + (size_t)bl * T_ * D_ + h * DH_;
    for (int i = tid; i < T_ * DH_; i += 256) {
        int t = i / DH_, d = i % DH_;
        float acc = 0.f;
        #pragma unroll 7
        for (int p = 0; p < P_; p++) acc += s_ptit[t][p] * s_img[p][d];
        out_img[(size_t)t * D_ + d] = f2tf32(acc);
    }
    uint32_t* out_tit = attn + (size_t)IMG_TOK * D_ + (size_t)bl * P_ * D_ + h * DH_;
    for (int i = tid; i < P_ * DH_; i += 256) {
        int p = i / DH_, d = i % DH_;
        float acc = 0.f;
        #pragma unroll
        for (int t = 0; t < T_; t++) acc += s_pimg[p][t] * s_tit[t][d];
        out_tit[(size_t)p * D_ + d] = f2tf32(acc);
    }
}

// ---------------- residual + LayerNorm: 4 warps/block, one token per warp ----------------
__global__ void __launch_bounds__(128) ln_res_kernel(
    const float* __restrict__ hid, const float* __restrict__ ffn,
    const float* __restrict__ aimg, const float* __restrict__ bimg,
    const float* __restrict__ atit, const float* __restrict__ btit,
    float* __restrict__ out)
{
    int tok = blockIdx.x * 4 + (threadIdx.x >> 5);
    if (tok >= NTOK) return;
    const float* a  = (tok < IMG_TOK) ? aimg : atit;
    const float* bb = (tok < IMG_TOK) ? bimg : btit;
    const float* x  = ffn + (size_t)tok * D_;
    const float* hh = hid + (size_t)tok * D_;
    float* o        = out + (size_t)tok * D_;

    int lane = threadIdx.x & 31;
    float v[16];
    float s = 0.f;
    #pragma unroll
    for (int i = 0; i < 4; i++) {
        float4 t4 = *(const float4*)(x + lane * 4 + i * 128);
        v[i*4+0] = t4.x; v[i*4+1] = t4.y; v[i*4+2] = t4.z; v[i*4+3] = t4.w;
        s += t4.x + t4.y + t4.z + t4.w;
    }
    #pragma unroll
    for (int off = 16; off > 0; off >>= 1) s += __shfl_xor_sync(0xffffffffu, s, off);
    float mean = s * (1.f / 512.f);

    float sq = 0.f;
    #pragma unroll
    for (int i = 0; i < 16; i++) { float d = v[i] - mean; sq += d * d; }
    #pragma unroll
    for (int off = 16; off > 0; off >>= 1) sq += __shfl_xor_sync(0xffffffffu, sq, off);
    float stdv = sqrtf(sq * (1.f / 511.f));
    float inv = 1.f / (stdv + EPS_);

    #pragma unroll
    for (int i = 0; i < 4; i++) {
        int c0 = lane * 4 + i * 128;
        float4 a4 = *(const float4*)(a  + c0);
        float4 b4 = *(const float4*)(bb + c0);
        float4 h4 = *(const float4*)(hh + c0);
        float4 r;
        r.x = h4.x + a4.x * (v[i*4+0] - mean) * inv + b4.x;
        r.y = h4.y + a4.y * (v[i*4+1] - mean) * inv + b4.y;
        r.z = h4.z + a4.z * (v[i*4+2] - mean) * inv + b4.z;
        r.w = h4.w + a4.w * (v[i*4+3] - mean) * inv + b4.w;
        *(float4*)(o + c0) = r;
    }
}

// ---------------- launch ----------------
#define MTILES ((NTOK + 127) / 128)      // 432
#define SPLIT_TILE (IMG_TOK / 128)       // 125 (exact)

extern "C" void kernel_launch(void* const* d_in, const int* in_sizes, int n_in,
                              void* d_out, int out_size)
{
    const float* img         = (const float*)d_in[0];
    const float* title       = (const float*)d_in[1];
    const int*   mask        = (const int*)  d_in[2];
    const float* scale_img   = (const float*)d_in[3];
    const float* scale_title = (const float*)d_in[4];
    const float* w_proj      = (const float*)d_in[5];
    const float* b_proj      = (const float*)d_in[6];
    const float* w1_img      = (const float*)d_in[7];
    const float* b1_img      = (const float*)d_in[8];
    const float* w2_img      = (const float*)d_in[9];
    const float* b2_img      = (const float*)d_in[10];
    const float* w1_tit      = (const float*)d_in[11];
    const float* b1_tit      = (const float*)d_in[12];
    const float* w2_tit      = (const float*)d_in[13];
    const float* b2_tit      = (const float*)d_in[14];
    const float* ln_a_img    = (const float*)d_in[15];
    const float* ln_b_img    = (const float*)d_in[16];
    const float* ln_a_tit    = (const float*)d_in[17];
    const float* ln_b_tit    = (const float*)d_in[18];
    float* out = (float*)d_out;

    uint32_t *attn_t, *hid_t, *ffn1_t, *wbuf;
    float *hid, *ffn2;
    cudaGetSymbolAddress((void**)&attn_t, g_attn_t);
    cudaGetSymbolAddress((void**)&hid,    g_hid);
    cudaGetSymbolAddress((void**)&hid_t,  g_hid_t);
    cudaGetSymbolAddress((void**)&ffn1_t, g_ffn1_t);
    cudaGetSymbolAddress((void**)&ffn2,   g_ffn2);
    cudaGetSymbolAddress((void**)&wbuf,   g_wbuf);

    cudaFuncSetAttribute(mma_gemm, cudaFuncAttributeMaxDynamicSharedMemorySize, MM_SMEM);

    // 0) weights -> tf32 bits
    prep_w<<<(WTOTAL / 4 + 255) / 256, 256>>>(w_proj, w1_img, w1_tit, w2_img, w2_tit, wbuf);

    // 1) attention (writes tf32)
    attn_kernel<<<B_ * L_ * H_, 256>>>(img, title, mask, scale_img, scale_title, attn_t);

    // 2) shared projection: fp32 hid (residual) + tf32 hid_t (FFN1 input)
    mma_gemm<<<dim3(D_ / 128, MTILES), 256, MM_SMEM>>>(
        attn_t, wbuf + WOFF_PROJ, b_proj, wbuf + WOFF_PROJ, b_proj, MTILES,
        hid, hid_t, NTOK, D_, D_, 0);

    // 3) FFN1 (+GELU), both branches, tf32 output only
    mma_gemm<<<dim3(DFF_ / 128, MTILES), 256, MM_SMEM>>>(
        hid_t, wbuf + WOFF_W1I, b1_img, wbuf + WOFF_W1T, b1_tit, SPLIT_TILE,
        (float*)nullptr, ffn1_t, NTOK, DFF_, D_, 1);

    // 4) FFN2, both branches, fp32 output only
    mma_gemm<<<dim3(D_ / 128, MTILES), 256, MM_SMEM>>>(
        ffn1_t, wbuf + WOFF_W2I, b2_img, wbuf + WOFF_W2T, b2_tit, SPLIT_TILE,
        ffn2, (uint32_t*)nullptr, NTOK, D_, DFF_, 0);

    // 5) out = hid + LN(ffn2)
    ln_res_kernel<<<(NTOK + 3) / 4, 128>>>(hid, ffn2, ln_a_img, ln_b_img,
                                           ln_a_tit, ln_b_tit, out);
}

// round 13
// speedup vs baseline: 1.4353x; 1.0458x over previous
#include <cuda_runtime.h>
#include <cuda_fp16.h>
#include <math.h>
#include <stdint.h>

// Problem constants
#define B_   16
#define L_   50
#define P_   49
#define T_   20
#define D_   512
#define H_   8
#define DH_  64
#define DFF_ 2048
#define IMG_TOK (B_*L_*T_)   // 16000  (= 125 tiles of 128, exactly)
#define TIT_TOK (B_*L_*P_)   // 39200
#define NTOK (IMG_TOK + TIT_TOK)  // 55200
#define NEGV (-1000000000.0f)
#define EPS_ 1e-6f

// ---------------- scratch ----------------
__device__ __half  g_attn_h[NTOK * D_];               // attention out, fp16
__device__ float   g_hid   [NTOK * D_];               // proj out fp32 (residual)
__device__ __half  g_hid_h [NTOK * D_];               // proj out fp16 (FFN1 input)
__device__ __half  g_ffn1_h[(size_t)NTOK * DFF_];     // gelu out fp16 (FFN2 input)
__device__ float   g_ffn2  [NTOK * D_];               // FFN2 out fp32 (LN input)

// pre-converted weights (fp16), packed segments
#define WOFF_PROJ 0
#define WOFF_W1I  (512*512)
#define WOFF_W1T  (WOFF_W1I + 2048*512)
#define WOFF_W2I  (WOFF_W1T + 2048*512)
#define WOFF_W2T  (WOFF_W2I + 512*2048)
#define WTOTAL    (WOFF_W2T + 512*2048)   // 4456448
__device__ __half g_wbuf[WTOTAL];

// gelu_tanh(x) = 0.5 x (1 + tanh(u)) = x * sigmoid(2u),  u = sqrt(2/pi)(x + 0.044715 x^3)
__device__ __forceinline__ float gelu_t(float x) {
    float x3 = x * x * x;
    float u = 0.7978845608028654f * (x + 0.044715f * x3);
    return __fdividef(x, 1.f + __expf(-2.f * u));
}
__device__ __forceinline__ void mma_f16(float* c, const uint32_t* a, const uint32_t* b) {
    asm volatile(
        "mma.sync.aligned.m16n8k16.row.col.f32.f16.f16.f32 "
        "{%0,%1,%2,%3}, {%4,%5,%6,%7}, {%8,%9}, {%0,%1,%2,%3};"
        : "+f"(c[0]), "+f"(c[1]), "+f"(c[2]), "+f"(c[3])
        : "r"(a[0]), "r"(a[1]), "r"(a[2]), "r"(a[3]), "r"(b[0]), "r"(b[1]));
}
__device__ __forceinline__ void ldsm4(uint32_t& r0, uint32_t& r1, uint32_t& r2, uint32_t& r3,
                                      uint32_t addr) {
    asm volatile("ldmatrix.sync.aligned.m8n8.x4.shared.b16 {%0,%1,%2,%3}, [%4];"
                 : "=r"(r0), "=r"(r1), "=r"(r2), "=r"(r3) : "r"(addr));
}
__device__ __forceinline__ void cp_async16(uint32_t dst, const void* src, uint32_t nbytes) {
    asm volatile("cp.async.cg.shared.global [%0], [%1], 16, %2;"
                 :: "r"(dst), "l"(src), "r"(nbytes));
}
__device__ __forceinline__ void cp_commit() {
    asm volatile("cp.async.commit_group;" ::: "memory");
}
template <int N>
__device__ __forceinline__ void cp_wait() {
    asm volatile("cp.async.wait_group %0;" :: "n"(N) : "memory");
}

// ---------------- weight pre-conversion (fp32 -> fp16) ----------------
__global__ void __launch_bounds__(256) prep_w(
    const float* __restrict__ a0, const float* __restrict__ a1,
    const float* __restrict__ a2, const float* __restrict__ a3,
    const float* __restrict__ a4, __half* __restrict__ o)
{
    size_t i = ((size_t)blockIdx.x * 256 + threadIdx.x) * 4;
    if (i >= WTOTAL) return;
    const float* src; size_t off;
    if      (i < WOFF_W1I) { src = a0; off = i; }
    else if (i < WOFF_W1T) { src = a1; off = i - WOFF_W1I; }
    else if (i < WOFF_W2I) { src = a2; off = i - WOFF_W1T; }
    else if (i < WOFF_W2T) { src = a3; off = i - WOFF_W2I; }
    else                   { src = a4; off = i - WOFF_W2T; }
    float4 v = *(const float4*)(src + off);
    __half2 h01 = __floats2half2_rn(v.x, v.y);
    __half2 h23 = __floats2half2_rn(v.z, v.w);
    *(__half2*)(o + i)     = h01;
    *(__half2*)(o + i + 2) = h23;
}

// ---------------- tensor-core GEMM via mma.sync fp16 + 2-stage cp.async ----------------
// A,W pre-converted fp16. Fragment loads via ldmatrix.x4 (same per-lane address
// formulas as the validated tf32 version; k-step = 16 halves = 32 B).
// K-chunk = 64 halves = 128 B/row (+16 B pad). fp32 accumulate.
#define SROWB 144u                    // smem row stride in bytes (128 data + 16 pad)
#define TILE_BYTES (128 * 144)        // 18432 B per matrix per buffer
#define MM_SMEM (4 * TILE_BYTES)      // 73728 B

__global__ void __launch_bounds__(256, 2) mma_gemm(
    const __half* __restrict__ A,
    const __half* __restrict__ W0, const float* __restrict__ b0,
    const __half* __restrict__ W1, const float* __restrict__ b1,
    int split_tile,
    float* __restrict__ Cf, __half* __restrict__ Ch,
    int M, int N, int K, int act)
{
    extern __shared__ uint32_t sh[];
    const uint32_t sm_base = (uint32_t)__cvta_generic_to_shared(sh);
    const uint32_t aU0 = sm_base;
    const uint32_t aU1 = sm_base + TILE_BYTES;
    const uint32_t bU0 = sm_base + 2 * TILE_BYTES;
    const uint32_t bU1 = sm_base + 3 * TILE_BYTES;

    const int tid = threadIdx.x;
    const int m0 = blockIdx.y * 128, n0 = blockIdx.x * 128;
    const __half* W   = (blockIdx.y < split_tile) ? W0 : W1;
    const float* bias = (blockIdx.y < split_tile) ? b0 : b1;

    const int w = tid >> 5, lane = tid & 31;
    const int wm = w & 3, wn = w >> 2;          // warp tile: rows wm*32, cols wn*64
    const int group = lane >> 2, quad = lane & 3;

    const int lrow0 = tid >> 3;        // copy mapping: rows lrow0 + t*32
    const int lc4   = tid & 7;         // 16B column (8 halves)

    // ldmatrix per-thread byte offsets within a tile (identical structure to tf32 ver.)
    const uint32_t aOff = (uint32_t)((wm * 32 + (lane & 15)) * SROWB + ((lane >> 4) << 4));
    const uint32_t bOff = (uint32_t)((wn * 64 + (lane & 7) + ((lane >> 4) << 3)) * SROWB
                                     + (((lane >> 3) & 1) << 4));

    float acc[2][8][4];
    #pragma unroll
    for (int i = 0; i < 2; i++)
        #pragma unroll
        for (int j = 0; j < 8; j++)
            #pragma unroll
            for (int q = 0; q < 4; q++) acc[i][j][q] = 0.f;

    const int nch = K >> 6;            // K/64: 8 (K=512) or 32 (K=2048) — even

    auto issue = [&](uint32_t aU, uint32_t bU, int kc) {   // kc in halves
        #pragma unroll
        for (int t = 0; t < 4; t++) {
            int row = lrow0 + t * 32;
            uint32_t off = (uint32_t)(row * SROWB + lc4 * 16);
            size_t arow = (m0 + row < M) ? (size_t)(m0 + row) : 0;
            cp_async16(aU + off, A + arow * K + kc + lc4 * 8,
                       (m0 + row < M) ? 16u : 0u);
            cp_async16(bU + off, W + (size_t)(n0 + row) * K + kc + lc4 * 8, 16u);
        }
        cp_commit();
    };

    auto compute = [&](uint32_t aT, uint32_t bT) {
        const uint32_t aA = aT + aOff;
        const uint32_t bA = bT + bOff;
        #pragma unroll
        for (int ks = 0; ks < 4; ks++) {
            const uint32_t k0b = ks * 32;          // 16 halves = 32 B per k-step
            uint32_t afr[2][4];
            ldsm4(afr[0][0], afr[0][1], afr[0][2], afr[0][3], aA + k0b);
            ldsm4(afr[1][0], afr[1][1], afr[1][2], afr[1][3], aA + 16 * SROWB + k0b);
            uint32_t bfr[8][2];
            #pragma unroll
            for (int nn = 0; nn < 4; nn++)
                ldsm4(bfr[2*nn][0], bfr[2*nn][1], bfr[2*nn+1][0], bfr[2*nn+1][1],
                      bA + (uint32_t)nn * 16 * SROWB + k0b);
            #pragma unroll
            for (int mi = 0; mi < 2; mi++)
                #pragma unroll
                for (int ni = 0; ni < 8; ni++)
                    mma_f16(acc[mi][ni], afr[mi], bfr[ni]);
        }
    };

    // prologue
    issue(aU0, bU0, 0);

    // mainloop: unrolled by 2, literal stage addresses, proven schedule
    for (int c = 0; c < nch; c += 2) {
        issue(aU1, bU1, (c + 1) << 6);       // c+1 < nch always (nch even)
        cp_wait<1>();
        __syncthreads();
        compute(aU0, bU0);
        __syncthreads();
        if (c + 2 < nch) {
            issue(aU0, bU0, (c + 2) << 6);
            cp_wait<1>();
        } else {
            cp_wait<0>();
        }
        __syncthreads();
        compute(aU1, bU1);
        __syncthreads();
    }

    // epilogue: bias + optional GELU; fp32 and/or fp16 outputs
    #pragma unroll
    for (int ni = 0; ni < 8; ni++) {
        int cc = n0 + wn * 64 + ni * 8 + quad * 2;
        float2 b2 = *(const float2*)(bias + cc);
        #pragma unroll
        for (int mi = 0; mi < 2; mi++) {
            #pragma unroll
            for (int half = 0; half < 2; half++) {
                int r = m0 + wm * 32 + mi * 16 + half * 8 + group;
                if (r >= M) continue;
                float2 v;
                v.x = acc[mi][ni][half * 2 + 0] + b2.x;
                v.y = acc[mi][ni][half * 2 + 1] + b2.y;
                if (act) { v.x = gelu_t(v.x); v.y = gelu_t(v.y); }
                if (Cf) *(float2*)(Cf + (size_t)r * N + cc) = v;
                if (Ch) *(__half2*)(Ch + (size_t)r * N + cc) = __floats2half2_rn(v.x, v.y);
            }
        }
    }
}

// ---------------- attention kernel (fp32 compute, fp16 output) ----------------
__global__ void __launch_bounds__(256) attn_kernel(
    const float* __restrict__ img, const float* __restrict__ title,
    const int* __restrict__ mask,
    const float* __restrict__ scale_img, const float* __restrict__ scale_title,
    __half* __restrict__ attn)
{
    int blk = blockIdx.x;
    int h  = blk % H_;
    int bl = blk / H_;

    const float* imgp = img   + (size_t)bl * P_ * D_ + h * DH_;
    const float* titp = title + (size_t)bl * T_ * D_ + h * DH_;
    const int*   mp   = mask  + bl * T_;

    __shared__ float s_img[P_][DH_ + 1];
    __shared__ float s_tit[T_][DH_ + 1];
    __shared__ float s_raw [P_][T_];
    __shared__ float s_pimg[P_][T_];
    __shared__ float s_ptit[T_][P_];
    __shared__ float s_mask[T_];

    int tid = threadIdx.x;

    for (int i = tid; i < P_ * DH_; i += 256) {
        int p = i / DH_, d = i % DH_;
        s_img[p][d] = imgp[(size_t)p * D_ + d];
    }
    for (int i = tid; i < T_ * DH_; i += 256) {
        int t = i / DH_, d = i % DH_;
        s_tit[t][d] = titp[(size_t)t * D_ + d];
    }
    if (tid < T_) s_mask[tid] = (float)mp[tid];
    __syncthreads();

    for (int i = tid; i < P_ * T_; i += 256) {
        int p = i / T_, t = i % T_;
        float acc = 0.f;
        #pragma unroll
        for (int d = 0; d < DH_; d++) acc += s_img[p][d] * s_tit[t][d];
        s_raw[p][t] = acc * 0.125f;
    }
    __syncthreads();

    if (tid < P_) {
        int p = tid;
        float sc = scale_img[h * P_ + p];
        float row[T_];
        float mx = -INFINITY;
        #pragma unroll
        for (int t = 0; t < T_; t++) {
            float v = (s_mask[t] != 0.f) ? s_raw[p][t] * sc : NEGV;
            row[t] = v;
            mx = fmaxf(mx, v);
        }
        float sum = 0.f;
        #pragma unroll
        for (int t = 0; t < T_; t++) { float e = __expf(row[t] - mx); row[t] = e; sum += e; }
        float inv = 1.f / sum;
        #pragma unroll
        for (int t = 0; t < T_; t++) s_pimg[p][t] = row[t] * inv;
    }
    if (tid >= 64 && tid < 64 + T_) {
        int t = tid - 64;
        float sc = scale_title[h * T_ + t];
        bool dead = (s_mask[t] == 0.f);
        float mx = -INFINITY;
        for (int p = 0; p < P_; p++) {
            float v = dead ? NEGV : s_raw[p][t] * sc;
            mx = fmaxf(mx, v);
        }
        float sum = 0.f;
        for (int p = 0; p < P_; p++) {
            float v = dead ? NEGV : s_raw[p][t] * sc;
            float e = __expf(v - mx);
            s_ptit[t][p] = e;
            sum += e;
        }
        float inv = 1.f / sum;
        for (int p = 0; p < P_; p++) s_ptit[t][p] *= inv;
    }
    __syncthreads();

    __half* out_img = attn + (size_t)bl * T_ * D_ + h * DH_;
    for (int i = tid; i < T_ * DH_; i += 256) {
        int t = i / DH_, d = i % DH_;
        float acc = 0.f;
        #pragma unroll 7
        for (int p = 0; p < P_; p++) acc += s_ptit[t][p] * s_img[p][d];
        out_img[(size_t)t * D_ + d] = __float2half_rn(acc);
    }
    __half* out_tit = attn + (size_t)IMG_TOK * D_ + (size_t)bl * P_ * D_ + h * DH_;
    for (int i = tid; i < P_ * DH_; i += 256) {
        int p = i / DH_, d = i % DH_;
        float acc = 0.f;
        #pragma unroll
        for (int t = 0; t < T_; t++) acc += s_pimg[p][t] * s_tit[t][d];
        out_tit[(size_t)p * D_ + d] = __float2half_rn(acc);
    }
}

// ---------------- residual + LayerNorm: 4 warps/block, one token per warp ----------------
__global__ void __launch_bounds__(128) ln_res_kernel(
    const float* __restrict__ hid, const float* __restrict__ ffn,
    const float* __restrict__ aimg, const float* __restrict__ bimg,
    const float* __restrict__ atit, const float* __restrict__ btit,
    float* __restrict__ out)
{
    int tok = blockIdx.x * 4 + (threadIdx.x >> 5);
    if (tok >= NTOK) return;
    const float* a  = (tok < IMG_TOK) ? aimg : atit;
    const float* bb = (tok < IMG_TOK) ? bimg : btit;
    const float* x  = ffn + (size_t)tok * D_;
    const float* hh = hid + (size_t)tok * D_;
    float* o        = out + (size_t)tok * D_;

    int lane = threadIdx.x & 31;
    float v[16];
    float s = 0.f;
    #pragma unroll
    for (int i = 0; i < 4; i++) {
        float4 t4 = *(const float4*)(x + lane * 4 + i * 128);
        v[i*4+0] = t4.x; v[i*4+1] = t4.y; v[i*4+2] = t4.z; v[i*4+3] = t4.w;
        s += t4.x + t4.y + t4.z + t4.w;
    }
    #pragma unroll
    for (int off = 16; off > 0; off >>= 1) s += __shfl_xor_sync(0xffffffffu, s, off);
    float mean = s * (1.f / 512.f);

    float sq = 0.f;
    #pragma unroll
    for (int i = 0; i < 16; i++) { float d = v[i] - mean; sq += d * d; }
    #pragma unroll
    for (int off = 16; off > 0; off >>= 1) sq += __shfl_xor_sync(0xffffffffu, sq, off);
    float stdv = sqrtf(sq * (1.f / 511.f));
    float inv = 1.f / (stdv + EPS_);

    #pragma unroll
    for (int i = 0; i < 4; i++) {
        int c0 = lane * 4 + i * 128;
        float4 a4 = *(const float4*)(a  + c0);
        float4 b4 = *(const float4*)(bb + c0);
        float4 h4 = *(const float4*)(hh + c0);
        float4 r;
        r.x = h4.x + a4.x * (v[i*4+0] - mean) * inv + b4.x;
        r.y = h4.y + a4.y * (v[i*4+1] - mean) * inv + b4.y;
        r.z = h4.z + a4.z * (v[i*4+2] - mean) * inv + b4.z;
        r.w = h4.w + a4.w * (v[i*4+3] - mean) * inv + b4.w;
        *(float4*)(o + c0) = r;
    }
}

// ---------------- launch ----------------
#define MTILES ((NTOK + 127) / 128)      // 432
#define SPLIT_TILE (IMG_TOK / 128)       // 125 (exact)

extern "C" void kernel_launch(void* const* d_in, const int* in_sizes, int n_in,
                              void* d_out, int out_size)
{
    const float* img         = (const float*)d_in[0];
    const float* title       = (const float*)d_in[1];
    const int*   mask        = (const int*)  d_in[2];
    const float* scale_img   = (const float*)d_in[3];
    const float* scale_title = (const float*)d_in[4];
    const float* w_proj      = (const float*)d_in[5];
    const float* b_proj      = (const float*)d_in[6];
    const float* w1_img      = (const float*)d_in[7];
    const float* b1_img      = (const float*)d_in[8];
    const float* w2_img      = (const float*)d_in[9];
    const float* b2_img      = (const float*)d_in[10];
    const float* w1_tit      = (const float*)d_in[11];
    const float* b1_tit      = (const float*)d_in[12];
    const float* w2_tit      = (const float*)d_in[13];
    const float* b2_tit      = (const float*)d_in[14];
    const float* ln_a_img    = (const float*)d_in[15];
    const float* ln_b_img    = (const float*)d_in[16];
    const float* ln_a_tit    = (const float*)d_in[17];
    const float* ln_b_tit    = (const float*)d_in[18];
    float* out = (float*)d_out;

    __half *attn_h, *hid_h, *ffn1_h, *wbuf;
    float *hid, *ffn2;
    cudaGetSymbolAddress((void**)&attn_h, g_attn_h);
    cudaGetSymbolAddress((void**)&hid,    g_hid);
    cudaGetSymbolAddress((void**)&hid_h,  g_hid_h);
    cudaGetSymbolAddress((void**)&ffn1_h, g_ffn1_h);
    cudaGetSymbolAddress((void**)&ffn2,   g_ffn2);
    cudaGetSymbolAddress((void**)&wbuf,   g_wbuf);

    cudaFuncSetAttribute(mma_gemm, cudaFuncAttributeMaxDynamicSharedMemorySize, MM_SMEM);

    // 0) weights -> fp16
    prep_w<<<(WTOTAL / 4 + 255) / 256, 256>>>(w_proj, w1_img, w1_tit, w2_img, w2_tit, wbuf);

    // 1) attention (writes fp16)
    attn_kernel<<<B_ * L_ * H_, 256>>>(img, title, mask, scale_img, scale_title, attn_h);

    // 2) shared projection: fp32 hid (residual) + fp16 hid_h (FFN1 input)
    mma_gemm<<<dim3(D_ / 128, MTILES), 256, MM_SMEM>>>(
        attn_h, wbuf + WOFF_PROJ, b_proj, wbuf + WOFF_PROJ, b_proj, MTILES,
        hid, hid_h, NTOK, D_, D_, 0);

    // 3) FFN1 (+GELU), both branches, fp16 output only
    mma_gemm<<<dim3(DFF_ / 128, MTILES), 256, MM_SMEM>>>(
        hid_h, wbuf + WOFF_W1I, b1_img, wbuf + WOFF_W1T, b1_tit, SPLIT_TILE,
        (float*)nullptr, ffn1_h, NTOK, DFF_, D_, 1);

    // 4) FFN2, both branches, fp32 output only
    mma_gemm<<<dim3(D_ / 128, MTILES), 256, MM_SMEM>>>(
        ffn1_h, wbuf + WOFF_W2I, b2_img, wbuf + WOFF_W2T, b2_tit, SPLIT_TILE,
        ffn2, (__half*)nullptr, NTOK, D_, DFF_, 0);

    // 5) out = hid + LN(ffn2)
    ln_res_kernel<<<(NTOK + 3) / 4, 128>>>(hid, ffn2, ln_a_img, ln_b_img,
                                           ln_a_tit, ln_b_tit, out);
}

// round 14
// speedup vs baseline: 2.2130x; 1.5419x over previous
#include <cuda_runtime.h>
#include <cuda_fp16.h>
#include <math.h>
#include <stdint.h>

// Problem constants
#define B_   16
#define L_   50
#define P_   49
#define T_   20
#define D_   512
#define H_   8
#define DH_  64
#define DFF_ 2048
#define IMG_TOK (B_*L_*T_)   // 16000  (= 125 tiles of 128, exactly)
#define TIT_TOK (B_*L_*P_)   // 39200
#define NTOK (IMG_TOK + TIT_TOK)  // 55200
#define NEGV (-1000000000.0f)
#define EPS_ 1e-6f

// ---------------- scratch ----------------
__device__ __half  g_attn_h[NTOK * D_];               // attention out, fp16
__device__ float   g_hid   [NTOK * D_];               // proj out fp32 (residual)
__device__ __half  g_hid_h [NTOK * D_];               // proj out fp16 (FFN1 input)
__device__ __half  g_ffn1_h[(size_t)NTOK * DFF_];     // gelu out fp16 (FFN2 input)
__device__ float   g_ffn2  [NTOK * D_];               // FFN2 out fp32 (LN input)

// pre-converted weights (fp16), packed segments
#define WOFF_PROJ 0
#define WOFF_W1I  (512*512)
#define WOFF_W1T  (WOFF_W1I + 2048*512)
#define WOFF_W2I  (WOFF_W1T + 2048*512)
#define WOFF_W2T  (WOFF_W2I + 512*2048)
#define WTOTAL    (WOFF_W2T + 512*2048)   // 4456448
__device__ __half g_wbuf[WTOTAL];

// gelu_tanh(x) = 0.5 x (1 + tanh(u)) = x * sigmoid(2u),  u = sqrt(2/pi)(x + 0.044715 x^3)
__device__ __forceinline__ float gelu_t(float x) {
    float x3 = x * x * x;
    float u = 0.7978845608028654f * (x + 0.044715f * x3);
    return __fdividef(x, 1.f + __expf(-2.f * u));
}
__device__ __forceinline__ void mma_f16(float* c, const uint32_t* a, const uint32_t* b) {
    asm volatile(
        "mma.sync.aligned.m16n8k16.row.col.f32.f16.f16.f32 "
        "{%0,%1,%2,%3}, {%4,%5,%6,%7}, {%8,%9}, {%0,%1,%2,%3};"
        : "+f"(c[0]), "+f"(c[1]), "+f"(c[2]), "+f"(c[3])
        : "r"(a[0]), "r"(a[1]), "r"(a[2]), "r"(a[3]), "r"(b[0]), "r"(b[1]));
}
__device__ __forceinline__ void ldsm4(uint32_t& r0, uint32_t& r1, uint32_t& r2, uint32_t& r3,
                                      uint32_t addr) {
    asm volatile("ldmatrix.sync.aligned.m8n8.x4.shared.b16 {%0,%1,%2,%3}, [%4];"
                 : "=r"(r0), "=r"(r1), "=r"(r2), "=r"(r3) : "r"(addr));
}
__device__ __forceinline__ void cp_async16(uint32_t dst, const void* src, uint32_t nbytes) {
    asm volatile("cp.async.cg.shared.global [%0], [%1], 16, %2;"
                 :: "r"(dst), "l"(src), "r"(nbytes));
}
__device__ __forceinline__ void cp_commit() {
    asm volatile("cp.async.commit_group;" ::: "memory");
}
template <int N>
__device__ __forceinline__ void cp_wait() {
    asm volatile("cp.async.wait_group %0;" :: "n"(N) : "memory");
}

// ---------------- weight pre-conversion (fp32 -> fp16) ----------------
__global__ void __launch_bounds__(256) prep_w(
    const float* __restrict__ a0, const float* __restrict__ a1,
    const float* __restrict__ a2, const float* __restrict__ a3,
    const float* __restrict__ a4, __half* __restrict__ o)
{
    size_t i = ((size_t)blockIdx.x * 256 + threadIdx.x) * 4;
    if (i >= WTOTAL) return;
    const float* src; size_t off;
    if      (i < WOFF_W1I) { src = a0; off = i; }
    else if (i < WOFF_W1T) { src = a1; off = i - WOFF_W1I; }
    else if (i < WOFF_W2I) { src = a2; off = i - WOFF_W1T; }
    else if (i < WOFF_W2T) { src = a3; off = i - WOFF_W2I; }
    else                   { src = a4; off = i - WOFF_W2T; }
    float4 v = *(const float4*)(src + off);
    __half2 h01 = __floats2half2_rn(v.x, v.y);
    __half2 h23 = __floats2half2_rn(v.z, v.w);
    *(__half2*)(o + i)     = h01;
    *(__half2*)(o + i + 2) = h23;
}

// ---------------- tensor-core GEMM: fp16 mma.sync, 128x64 tile, 4 warps, 4 CTAs/SM ----------------
// Per-warp structure identical to the validated 128x128 version (warp tile 32x64),
// but each CTA is its own barrier domain of only 4 warps -> 4 independent
// pipelines per SM hide each other's chunk-boundary latency.
#define SROWB 144u                       // smem row stride bytes (128 data + 16 pad)
#define A_TILE_B (128 * 144)             // 18432 B per A buffer
#define B_TILE_B (64 * 144)              // 9216 B per B buffer
#define MM_SMEM (2 * A_TILE_B + 2 * B_TILE_B)   // 55296 B

__global__ void __launch_bounds__(128, 4) mma_gemm(
    const __half* __restrict__ A,
    const __half* __restrict__ W0, const float* __restrict__ b0,
    const __half* __restrict__ W1, const float* __restrict__ b1,
    int split_tile,
    float* __restrict__ Cf, __half* __restrict__ Ch,
    int M, int N, int K, int act)
{
    extern __shared__ uint32_t sh[];
    const uint32_t sm_base = (uint32_t)__cvta_generic_to_shared(sh);
    const uint32_t aU0 = sm_base;
    const uint32_t aU1 = sm_base + A_TILE_B;
    const uint32_t bU0 = sm_base + 2 * A_TILE_B;
    const uint32_t bU1 = sm_base + 2 * A_TILE_B + B_TILE_B;

    const int tid = threadIdx.x;
    const int m0 = blockIdx.y * 128, n0 = blockIdx.x * 64;
    const __half* W   = (blockIdx.y < split_tile) ? W0 : W1;
    const float* bias = (blockIdx.y < split_tile) ? b0 : b1;

    const int w = tid >> 5, lane = tid & 31;
    const int wm = w;                          // warp tile: rows wm*32, all 64 cols
    const int group = lane >> 2, quad = lane & 3;

    const int lrow0 = tid >> 3;        // copy mapping: rows lrow0 + t*16
    const int lc4   = tid & 7;         // 16B column (8 halves)

    // ldmatrix per-thread byte offsets within a tile
    const uint32_t aOff = (uint32_t)((wm * 32 + (lane & 15)) * SROWB + ((lane >> 4) << 4));
    const uint32_t bOff = (uint32_t)(((lane & 7) + ((lane >> 4) << 3)) * SROWB
                                     + (((lane >> 3) & 1) << 4));

    float acc[2][8][4];
    #pragma unroll
    for (int i = 0; i < 2; i++)
        #pragma unroll
        for (int j = 0; j < 8; j++)
            #pragma unroll
            for (int q = 0; q < 4; q++) acc[i][j][q] = 0.f;

    const int nch = K >> 6;            // K/64: 8 (K=512) or 32 (K=2048) — even

    auto issue = [&](uint32_t aU, uint32_t bU, int kc) {   // kc in halves
        #pragma unroll
        for (int t = 0; t < 8; t++) {                       // A: 128 rows
            int row = lrow0 + t * 16;
            uint32_t off = (uint32_t)(row * SROWB + lc4 * 16);
            size_t arow = (m0 + row < M) ? (size_t)(m0 + row) : 0;
            cp_async16(aU + off, A + arow * K + kc + lc4 * 8,
                       (m0 + row < M) ? 16u : 0u);
        }
        #pragma unroll
        for (int t = 0; t < 4; t++) {                       // B: 64 rows
            int row = lrow0 + t * 16;
            uint32_t off = (uint32_t)(row * SROWB + lc4 * 16);
            cp_async16(bU + off, W + (size_t)(n0 + row) * K + kc + lc4 * 8, 16u);
        }
        cp_commit();
    };

    auto compute = [&](uint32_t aT, uint32_t bT) {
        const uint32_t aA = aT + aOff;
        const uint32_t bA = bT + bOff;
        #pragma unroll
        for (int ks = 0; ks < 4; ks++) {
            const uint32_t k0b = ks * 32;          // 16 halves = 32 B per k-step
            uint32_t afr[2][4];
            ldsm4(afr[0][0], afr[0][1], afr[0][2], afr[0][3], aA + k0b);
            ldsm4(afr[1][0], afr[1][1], afr[1][2], afr[1][3], aA + 16 * SROWB + k0b);
            uint32_t bfr[8][2];
            #pragma unroll
            for (int nn = 0; nn < 4; nn++)
                ldsm4(bfr[2*nn][0], bfr[2*nn][1], bfr[2*nn+1][0], bfr[2*nn+1][1],
                      bA + (uint32_t)nn * 16 * SROWB + k0b);
            #pragma unroll
            for (int mi = 0; mi < 2; mi++)
                #pragma unroll
                for (int ni = 0; ni < 8; ni++)
                    mma_f16(acc[mi][ni], afr[mi], bfr[ni]);
        }
    };

    // prologue
    issue(aU0, bU0, 0);

    // mainloop: unrolled by 2, literal stage addresses, proven schedule
    for (int c = 0; c < nch; c += 2) {
        issue(aU1, bU1, (c + 1) << 6);       // c+1 < nch always (nch even)
        cp_wait<1>();
        __syncthreads();
        compute(aU0, bU0);
        __syncthreads();
        if (c + 2 < nch) {
            issue(aU0, bU0, (c + 2) << 6);
            cp_wait<1>();
        } else {
            cp_wait<0>();
        }
        __syncthreads();
        compute(aU1, bU1);
        __syncthreads();
    }

    // epilogue: bias + optional GELU; fp32 and/or fp16 outputs
    #pragma unroll
    for (int ni = 0; ni < 8; ni++) {
        int cc = n0 + ni * 8 + quad * 2;
        float2 b2 = *(const float2*)(bias + cc);
        #pragma unroll
        for (int mi = 0; mi < 2; mi++) {
            #pragma unroll
            for (int half = 0; half < 2; half++) {
                int r = m0 + wm * 32 + mi * 16 + half * 8 + group;
                if (r >= M) continue;
                float2 v;
                v.x = acc[mi][ni][half * 2 + 0] + b2.x;
                v.y = acc[mi][ni][half * 2 + 1] + b2.y;
                if (act) { v.x = gelu_t(v.x); v.y = gelu_t(v.y); }
                if (Cf) *(float2*)(Cf + (size_t)r * N + cc) = v;
                if (Ch) *(__half2*)(Ch + (size_t)r * N + cc) = __floats2half2_rn(v.x, v.y);
            }
        }
    }
}

// ---------------- attention kernel (fp32 compute, fp16 output) ----------------
__global__ void __launch_bounds__(256) attn_kernel(
    const float* __restrict__ img, const float* __restrict__ title,
    const int* __restrict__ mask,
    const float* __restrict__ scale_img, const float* __restrict__ scale_title,
    __half* __restrict__ attn)
{
    int blk = blockIdx.x;
    int h  = blk % H_;
    int bl = blk / H_;

    const float* imgp = img   + (size_t)bl * P_ * D_ + h * DH_;
    const float* titp = title + (size_t)bl * T_ * D_ + h * DH_;
    const int*   mp   = mask  + bl * T_;

    __shared__ float s_img[P_][DH_ + 1];
    __shared__ float s_tit[T_][DH_ + 1];
    __shared__ float s_raw [P_][T_];
    __shared__ float s_pimg[P_][T_];
    __shared__ float s_ptit[T_][P_];
    __shared__ float s_mask[T_];

    int tid = threadIdx.x;

    for (int i = tid; i < P_ * DH_; i += 256) {
        int p = i / DH_, d = i % DH_;
        s_img[p][d] = imgp[(size_t)p * D_ + d];
    }
    for (int i = tid; i < T_ * DH_; i += 256) {
        int t = i / DH_, d = i % DH_;
        s_tit[t][d] = titp[(size_t)t * D_ + d];
    }
    if (tid < T_) s_mask[tid] = (float)mp[tid];
    __syncthreads();

    for (int i = tid; i < P_ * T_; i += 256) {
        int p = i / T_, t = i % T_;
        float acc = 0.f;
        #pragma unroll
        for (int d = 0; d < DH_; d++) acc += s_img[p][d] * s_tit[t][d];
        s_raw[p][t] = acc * 0.125f;
    }
    __syncthreads();

    if (tid < P_) {
        int p = tid;
        float sc = scale_img[h * P_ + p];
        float row[T_];
        float mx = -INFINITY;
        #pragma unroll
        for (int t = 0; t < T_; t++) {
            float v = (s_mask[t] != 0.f) ? s_raw[p][t] * sc : NEGV;
            row[t] = v;
            mx = fmaxf(mx, v);
        }
        float sum = 0.f;
        #pragma unroll
        for (int t = 0; t < T_; t++) { float e = __expf(row[t] - mx); row[t] = e; sum += e; }
        float inv = 1.f / sum;
        #pragma unroll
        for (int t = 0; t < T_; t++) s_pimg[p][t] = row[t] * inv;
    }
    if (tid >= 64 && tid < 64 + T_) {
        int t = tid - 64;
        float sc = scale_title[h * T_ + t];
        bool dead = (s_mask[t] == 0.f);
        float mx = -INFINITY;
        for (int p = 0; p < P_; p++) {
            float v = dead ? NEGV : s_raw[p][t] * sc;
            mx = fmaxf(mx, v);
        }
        float sum = 0.f;
        for (int p = 0; p < P_; p++) {
            float v = dead ? NEGV : s_raw[p][t] * sc;
            float e = __expf(v - mx);
            s_ptit[t][p] = e;
            sum += e;
        }
        float inv = 1.f / sum;
        for (int p = 0; p < P_; p++) s_ptit[t][p] *= inv;
    }
    __syncthreads();

    __half* out_img = attn + (size_t)bl * T_ * D_ + h * DH_;
    for (int i = tid; i < T_ * DH_; i += 256) {
        int t = i / DH_, d = i % DH_;
        float acc = 0.f;
        #pragma unroll 7
        for (int p = 0; p < P_; p++) acc += s_ptit[t][p] * s_img[p][d];
        out_img[(size_t)t * D_ + d] = __float2half_rn(acc);
    }
    __half* out_tit = attn + (size_t)IMG_TOK * D_ + (size_t)bl * P_ * D_ + h * DH_;
    for (int i = tid; i < P_ * DH_; i += 256) {
        int p = i / DH_, d = i % DH_;
        float acc = 0.f;
        #pragma unroll
        for (int t = 0; t < T_; t++) acc += s_pimg[p][t] * s_tit[t][d];
        out_tit[(size_t)p * D_ + d] = __float2half_rn(acc);
    }
}

// ---------------- residual + LayerNorm: 4 warps/block, one token per warp ----------------
__global__ void __launch_bounds__(128) ln_res_kernel(
    const float* __restrict__ hid, const float* __restrict__ ffn,
    const float* __restrict__ aimg, const float* __restrict__ bimg,
    const float* __restrict__ atit, const float* __restrict__ btit,
    float* __restrict__ out)
{
    int tok = blockIdx.x * 4 + (threadIdx.x >> 5);
    if (tok >= NTOK) return;
    const float* a  = (tok < IMG_TOK) ? aimg : atit;
    const float* bb = (tok < IMG_TOK) ? bimg : btit;
    const float* x  = ffn + (size_t)tok * D_;
    const float* hh = hid + (size_t)tok * D_;
    float* o        = out + (size_t)tok * D_;

    int lane = threadIdx.x & 31;
    float v[16];
    float s = 0.f;
    #pragma unroll
    for (int i = 0; i < 4; i++) {
        float4 t4 = *(const float4*)(x + lane * 4 + i * 128);
        v[i*4+0] = t4.x; v[i*4+1] = t4.y; v[i*4+2] = t4.z; v[i*4+3] = t4.w;
        s += t4.x + t4.y + t4.z + t4.w;
    }
    #pragma unroll
    for (int off = 16; off > 0; off >>= 1) s += __shfl_xor_sync(0xffffffffu, s, off);
    float mean = s * (1.f / 512.f);

    float sq = 0.f;
    #pragma unroll
    for (int i = 0; i < 16; i++) { float d = v[i] - mean; sq += d * d; }
    #pragma unroll
    for (int off = 16; off > 0; off >>= 1) sq += __shfl_xor_sync(0xffffffffu, sq, off);
    float stdv = sqrtf(sq * (1.f / 511.f));
    float inv = 1.f / (stdv + EPS_);

    #pragma unroll
    for (int i = 0; i < 4; i++) {
        int c0 = lane * 4 + i * 128;
        float4 a4 = *(const float4*)(a  + c0);
        float4 b4 = *(const float4*)(bb + c0);
        float4 h4 = *(const float4*)(hh + c0);
        float4 r;
        r.x = h4.x + a4.x * (v[i*4+0] - mean) * inv + b4.x;
        r.y = h4.y + a4.y * (v[i*4+1] - mean) * inv + b4.y;
        r.z = h4.z + a4.z * (v[i*4+2] - mean) * inv + b4.z;
        r.w = h4.w + a4.w * (v[i*4+3] - mean) * inv + b4.w;
        *(float4*)(o + c0) = r;
    }
}

// ---------------- launch ----------------
#define MTILES ((NTOK + 127) / 128)      // 432
#define SPLIT_TILE (IMG_TOK / 128)       // 125 (exact)

extern "C" void kernel_launch(void* const* d_in, const int* in_sizes, int n_in,
                              void* d_out, int out_size)
{
    const float* img         = (const float*)d_in[0];
    const float* title       = (const float*)d_in[1];
    const int*   mask        = (const int*)  d_in[2];
    const float* scale_img   = (const float*)d_in[3];
    const float* scale_title = (const float*)d_in[4];
    const float* w_proj      = (const float*)d_in[5];
    const float* b_proj      = (const float*)d_in[6];
    const float* w1_img      = (const float*)d_in[7];
    const float* b1_img      = (const float*)d_in[8];
    const float* w2_img      = (const float*)d_in[9];
    const float* b2_img      = (const float*)d_in[10];
    const float* w1_tit      = (const float*)d_in[11];
    const float* b1_tit      = (const float*)d_in[12];
    const float* w2_tit      = (const float*)d_in[13];
    const float* b2_tit      = (const float*)d_in[14];
    const float* ln_a_img    = (const float*)d_in[15];
    const float* ln_b_img    = (const float*)d_in[16];
    const float* ln_a_tit    = (const float*)d_in[17];
    const float* ln_b_tit    = (const float*)d_in[18];
    float* out = (float*)d_out;

    __half *attn_h, *hid_h, *ffn1_h, *wbuf;
    float *hid, *ffn2;
    cudaGetSymbolAddress((void**)&attn_h, g_attn_h);
    cudaGetSymbolAddress((void**)&hid,    g_hid);
    cudaGetSymbolAddress((void**)&hid_h,  g_hid_h);
    cudaGetSymbolAddress((void**)&ffn1_h, g_ffn1_h);
    cudaGetSymbolAddress((void**)&ffn2,   g_ffn2);
    cudaGetSymbolAddress((void**)&wbuf,   g_wbuf);

    cudaFuncSetAttribute(mma_gemm, cudaFuncAttributeMaxDynamicSharedMemorySize, MM_SMEM);

    // 0) weights -> fp16
    prep_w<<<(WTOTAL / 4 + 255) / 256, 256>>>(w_proj, w1_img, w1_tit, w2_img, w2_tit, wbuf);

    // 1) attention (writes fp16)
    attn_kernel<<<B_ * L_ * H_, 256>>>(img, title, mask, scale_img, scale_title, attn_h);

    // 2) shared projection: fp32 hid (residual) + fp16 hid_h (FFN1 input)
    mma_gemm<<<dim3(D_ / 64, MTILES), 128, MM_SMEM>>>(
        attn_h, wbuf + WOFF_PROJ, b_proj, wbuf + WOFF_PROJ, b_proj, MTILES,
        hid, hid_h, NTOK, D_, D_, 0);

    // 3) FFN1 (+GELU), both branches, fp16 output only
    mma_gemm<<<dim3(DFF_ / 64, MTILES), 128, MM_SMEM>>>(
        hid_h, wbuf + WOFF_W1I, b1_img, wbuf + WOFF_W1T, b1_tit, SPLIT_TILE,
        (float*)nullptr, ffn1_h, NTOK, DFF_, D_, 1);

    // 4) FFN2, both branches, fp32 output only
    mma_gemm<<<dim3(D_ / 64, MTILES), 128, MM_SMEM>>>(
        ffn1_h, wbuf + WOFF_W2I, b2_img, wbuf + WOFF_W2T, b2_tit, SPLIT_TILE,
        ffn2, (__half*)nullptr, NTOK, D_, DFF_, 0);

    // 5) out = hid + LN(ffn2)
    ln_res_kernel<<<(NTOK + 3) / 4, 128>>>(hid, ffn2, ln_a_img, ln_b_img,
                                           ln_a_tit, ln_b_tit, out);
}

// round 16
// speedup vs baseline: 2.3803x; 1.0756x over previous
#include <cuda_runtime.h>
#include <cuda_fp16.h>
#include <math.h>
#include <stdint.h>

// Problem constants
#define B_   16
#define L_   50
#define P_   49
#define T_   20
#define D_   512
#define H_   8
#define DH_  64
#define DFF_ 2048
#define IMG_TOK (B_*L_*T_)   // 16000  (= 125 tiles of 128, exactly)
#define TIT_TOK (B_*L_*P_)   // 39200
#define NTOK (IMG_TOK + TIT_TOK)  // 55200
#define NEGV (-1000000000.0f)
#define EPS_ 1e-6f

// ---------------- scratch ----------------
__device__ __half  g_attn_h[NTOK * D_];               // attention out, fp16
__device__ __half  g_hid_h [NTOK * D_];               // proj out fp16 (residual + FFN1 input)
__device__ __half  g_ffn1_h[(size_t)NTOK * DFF_];     // gelu out fp16 (FFN2 input)
__device__ float   g_ffn2  [NTOK * D_];               // FFN2 out fp32 (LN input)

// pre-converted weights (fp16), packed segments
#define WOFF_PROJ 0
#define WOFF_W1I  (512*512)
#define WOFF_W1T  (WOFF_W1I + 2048*512)
#define WOFF_W2I  (WOFF_W1T + 2048*512)
#define WOFF_W2T  (WOFF_W2I + 512*2048)
#define WTOTAL    (WOFF_W2T + 512*2048)   // 4456448
__device__ __half g_wbuf[WTOTAL];

// gelu_tanh(x) = 0.5 x (1 + tanh(u)) = x * sigmoid(2u),  u = sqrt(2/pi)(x + 0.044715 x^3)
__device__ __forceinline__ float gelu_t(float x) {
    float x3 = x * x * x;
    float u = 0.7978845608028654f * (x + 0.044715f * x3);
    return __fdividef(x, 1.f + __expf(-2.f * u));
}
__device__ __forceinline__ void mma_f16(float* c, const uint32_t* a, const uint32_t* b) {
    asm volatile(
        "mma.sync.aligned.m16n8k16.row.col.f32.f16.f16.f32 "
        "{%0,%1,%2,%3}, {%4,%5,%6,%7}, {%8,%9}, {%0,%1,%2,%3};"
        : "+f"(c[0]), "+f"(c[1]), "+f"(c[2]), "+f"(c[3])
        : "r"(a[0]), "r"(a[1]), "r"(a[2]), "r"(a[3]), "r"(b[0]), "r"(b[1]));
}
__device__ __forceinline__ void ldsm4(uint32_t& r0, uint32_t& r1, uint32_t& r2, uint32_t& r3,
                                      uint32_t addr) {
    asm volatile("ldmatrix.sync.aligned.m8n8.x4.shared.b16 {%0,%1,%2,%3}, [%4];"
                 : "=r"(r0), "=r"(r1), "=r"(r2), "=r"(r3) : "r"(addr));
}
__device__ __forceinline__ void cp_async16(uint32_t dst, const void* src, uint32_t nbytes) {
    asm volatile("cp.async.cg.shared.global [%0], [%1], 16, %2;"
                 :: "r"(dst), "l"(src), "r"(nbytes));
}
__device__ __forceinline__ void cp_commit() {
    asm volatile("cp.async.commit_group;" ::: "memory");
}
template <int N>
__device__ __forceinline__ void cp_wait() {
    asm volatile("cp.async.wait_group %0;" :: "n"(N) : "memory");
}

// ---------------- weight pre-conversion (fp32 -> fp16) ----------------
__global__ void __launch_bounds__(256) prep_w(
    const float* __restrict__ a0, const float* __restrict__ a1,
    const float* __restrict__ a2, const float* __restrict__ a3,
    const float* __restrict__ a4, __half* __restrict__ o)
{
    size_t i = ((size_t)blockIdx.x * 256 + threadIdx.x) * 4;
    if (i >= WTOTAL) return;
    const float* src; size_t off;
    if      (i < WOFF_W1I) { src = a0; off = i; }
    else if (i < WOFF_W1T) { src = a1; off = i - WOFF_W1I; }
    else if (i < WOFF_W2I) { src = a2; off = i - WOFF_W1T; }
    else if (i < WOFF_W2T) { src = a3; off = i - WOFF_W2I; }
    else                   { src = a4; off = i - WOFF_W2T; }
    float4 v = *(const float4*)(src + off);
    __half2 h01 = __floats2half2_rn(v.x, v.y);
    __half2 h23 = __floats2half2_rn(v.z, v.w);
    *(__half2*)(o + i)     = h01;
    *(__half2*)(o + i + 2) = h23;
}

// ---------------- tensor-core GEMM: fp16 mma.sync, 128x64 tile, 4 warps, 4 CTAs/SM ----------------
#define SROWB 144u                       // smem row stride bytes (128 data + 16 pad)
#define A_TILE_B (128 * 144)             // 18432 B per A buffer
#define B_TILE_B (64 * 144)              // 9216 B per B buffer
#define MM_SMEM (2 * A_TILE_B + 2 * B_TILE_B)   // 55296 B

__global__ void __launch_bounds__(128, 4) mma_gemm(
    const __half* __restrict__ A,
    const __half* __restrict__ W0, const float* __restrict__ b0,
    const __half* __restrict__ W1, const float* __restrict__ b1,
    int split_tile,
    float* __restrict__ Cf, __half* __restrict__ Ch,
    int M, int N, int K, int act)
{
    extern __shared__ uint32_t sh[];
    const uint32_t sm_base = (uint32_t)__cvta_generic_to_shared(sh);
    const uint32_t aU0 = sm_base;
    const uint32_t aU1 = sm_base + A_TILE_B;
    const uint32_t bU0 = sm_base + 2 * A_TILE_B;
    const uint32_t bU1 = sm_base + 2 * A_TILE_B + B_TILE_B;

    const int tid = threadIdx.x;
    const int m0 = blockIdx.y * 128, n0 = blockIdx.x * 64;
    const __half* W   = (blockIdx.y < split_tile) ? W0 : W1;
    const float* bias = (blockIdx.y < split_tile) ? b0 : b1;

    const int w = tid >> 5, lane = tid & 31;
    const int wm = w;                          // warp tile: rows wm*32, all 64 cols
    const int group = lane >> 2, quad = lane & 3;

    const int lrow0 = tid >> 3;        // copy mapping: rows lrow0 + t*16
    const int lc4   = tid & 7;         // 16B column (8 halves)

    const uint32_t aOff = (uint32_t)((wm * 32 + (lane & 15)) * SROWB + ((lane >> 4) << 4));
    const uint32_t bOff = (uint32_t)(((lane & 7) + ((lane >> 4) << 3)) * SROWB
                                     + (((lane >> 3) & 1) << 4));

    float acc[2][8][4];
    #pragma unroll
    for (int i = 0; i < 2; i++)
        #pragma unroll
        for (int j = 0; j < 8; j++)
            #pragma unroll
            for (int q = 0; q < 4; q++) acc[i][j][q] = 0.f;

    const int nch = K >> 6;            // K/64: 8 (K=512) or 32 (K=2048) — even

    auto issue = [&](uint32_t aU, uint32_t bU, int kc) {   // kc in halves
        #pragma unroll
        for (int t = 0; t < 8; t++) {                       // A: 128 rows
            int row = lrow0 + t * 16;
            uint32_t off = (uint32_t)(row * SROWB + lc4 * 16);
            size_t arow = (m0 + row < M) ? (size_t)(m0 + row) : 0;
            cp_async16(aU + off, A + arow * K + kc + lc4 * 8,
                       (m0 + row < M) ? 16u : 0u);
        }
        #pragma unroll
        for (int t = 0; t < 4; t++) {                       // B: 64 rows
            int row = lrow0 + t * 16;
            uint32_t off = (uint32_t)(row * SROWB + lc4 * 16);
            cp_async16(bU + off, W + (size_t)(n0 + row) * K + kc + lc4 * 8, 16u);
        }
        cp_commit();
    };

    auto compute = [&](uint32_t aT, uint32_t bT) {
        const uint32_t aA = aT + aOff;
        const uint32_t bA = bT + bOff;
        #pragma unroll
        for (int ks = 0; ks < 4; ks++) {
            const uint32_t k0b = ks * 32;          // 16 halves = 32 B per k-step
            uint32_t afr[2][4];
            ldsm4(afr[0][0], afr[0][1], afr[0][2], afr[0][3], aA + k0b);
            ldsm4(afr[1][0], afr[1][1], afr[1][2], afr[1][3], aA + 16 * SROWB + k0b);
            uint32_t bfr[8][2];
            #pragma unroll
            for (int nn = 0; nn < 4; nn++)
                ldsm4(bfr[2*nn][0], bfr[2*nn][1], bfr[2*nn+1][0], bfr[2*nn+1][1],
                      bA + (uint32_t)nn * 16 * SROWB + k0b);
            #pragma unroll
            for (int mi = 0; mi < 2; mi++)
                #pragma unroll
                for (int ni = 0; ni < 8; ni++)
                    mma_f16(acc[mi][ni], afr[mi], bfr[ni]);
        }
    };

    // prologue
    issue(aU0, bU0, 0);

    for (int c = 0; c < nch; c += 2) {
        issue(aU1, bU1, (c + 1) << 6);       // c+1 < nch always (nch even)
        cp_wait<1>();
        __syncthreads();
        compute(aU0, bU0);
        __syncthreads();
        if (c + 2 < nch) {
            issue(aU0, bU0, (c + 2) << 6);
            cp_wait<1>();
        } else {
            cp_wait<0>();
        }
        __syncthreads();
        compute(aU1, bU1);
        __syncthreads();
    }

    // epilogue: bias + optional GELU; fp32 and/or fp16 outputs
    #pragma unroll
    for (int ni = 0; ni < 8; ni++) {
        int cc = n0 + ni * 8 + quad * 2;
        float2 b2 = *(const float2*)(bias + cc);
        #pragma unroll
        for (int mi = 0; mi < 2; mi++) {
            #pragma unroll
            for (int half = 0; half < 2; half++) {
                int r = m0 + wm * 32 + mi * 16 + half * 8 + group;
                if (r >= M) continue;
                float2 v;
                v.x = acc[mi][ni][half * 2 + 0] + b2.x;
                v.y = acc[mi][ni][half * 2 + 1] + b2.y;
                if (act) { v.x = gelu_t(v.x); v.y = gelu_t(v.y); }
                if (Cf) *(float2*)(Cf + (size_t)r * N + cc) = v;
                if (Ch) *(__half2*)(Ch + (size_t)r * N + cc) = __floats2half2_rn(v.x, v.y);
            }
        }
    }
}

// ---------------- attention kernel: fp16 smem operands, half2-vectorized loops ----------------
#define ISTR 66   // s_img/s_tit row stride in halves (132 B): bank-clean for both patterns

__global__ void __launch_bounds__(256) attn_kernel(
    const float* __restrict__ img, const float* __restrict__ title,
    const int* __restrict__ mask,
    const float* __restrict__ scale_img, const float* __restrict__ scale_title,
    __half* __restrict__ attn)
{
    int blk = blockIdx.x;
    int h  = blk % H_;
    int bl = blk / H_;

    const float* imgp = img   + (size_t)bl * P_ * D_ + h * DH_;
    const float* titp = title + (size_t)bl * T_ * D_ + h * DH_;
    const int*   mp   = mask  + bl * T_;

    __shared__ __half s_img[P_ * ISTR];
    __shared__ __half s_tit[T_ * ISTR];
    __shared__ float  s_raw [P_][T_];
    __shared__ float  s_pimg[P_][T_];
    __shared__ float  s_ptit[T_][P_];
    __shared__ float  s_mask[T_];

    int tid = threadIdx.x;

    for (int i = tid; i < P_ * DH_; i += 256) {
        int p = i >> 6, d = i & 63;
        s_img[p * ISTR + d] = __float2half_rn(imgp[(size_t)p * D_ + d]);
    }
    for (int i = tid; i < T_ * DH_; i += 256) {
        int t = i >> 6, d = i & 63;
        s_tit[t * ISTR + d] = __float2half_rn(titp[(size_t)t * D_ + d]);
    }
    if (tid < T_) s_mask[tid] = (float)mp[tid];
    __syncthreads();

    // raw[p][t] = (img_p . tit_t) / 8   (half2 operands, fp32 accumulate)
    for (int i = tid; i < P_ * T_; i += 256) {
        int p = i / T_, t = i % T_;
        const __half2* ip = (const __half2*)(s_img + p * ISTR);
        const __half2* tp = (const __half2*)(s_tit + t * ISTR);
        float acc = 0.f;
        #pragma unroll
        for (int d2 = 0; d2 < 32; d2++) {
            float2 a = __half22float2(ip[d2]);
            float2 b = __half22float2(tp[d2]);
            acc += a.x * b.x + a.y * b.y;
        }
        s_raw[p][t] = acc * 0.125f;
    }
    __syncthreads();

    if (tid < P_) {
        int p = tid;
        float sc = scale_img[h * P_ + p];
        float row[T_];
        float mx = -INFINITY;
        #pragma unroll
        for (int t = 0; t < T_; t++) {
            float v = (s_mask[t] != 0.f) ? s_raw[p][t] * sc : NEGV;
            row[t] = v;
            mx = fmaxf(mx, v);
        }
        float sum = 0.f;
        #pragma unroll
        for (int t = 0; t < T_; t++) { float e = __expf(row[t] - mx); row[t] = e; sum += e; }
        float inv = 1.f / sum;
        #pragma unroll
        for (int t = 0; t < T_; t++) s_pimg[p][t] = row[t] * inv;
    }
    if (tid >= 64 && tid < 64 + T_) {
        int t = tid - 64;
        float sc = scale_title[h * T_ + t];
        bool dead = (s_mask[t] == 0.f);
        float mx = -INFINITY;
        for (int p = 0; p < P_; p++) {
            float v = dead ? NEGV : s_raw[p][t] * sc;
            mx = fmaxf(mx, v);
        }
        float sum = 0.f;
        for (int p = 0; p < P_; p++) {
            float v = dead ? NEGV : s_raw[p][t] * sc;
            float e = __expf(v - mx);
            s_ptit[t][p] = e;
            sum += e;
        }
        float inv = 1.f / sum;
        for (int p = 0; p < P_; p++) s_ptit[t][p] *= inv;
    }
    __syncthreads();

    // attn_img[t, 2*d2..] = sum_p ptit[t][p] * img[p][2*d2..]  (warp per t: 32 lanes x half2)
    __half* out_img = attn + (size_t)bl * T_ * D_ + h * DH_;
    for (int i = tid; i < T_ * 32; i += 256) {
        int t = i >> 5, d2 = i & 31;
        const __half2* ip = (const __half2*)s_img + d2;   // + p*(ISTR/2) per row
        float2 acc = make_float2(0.f, 0.f);
        #pragma unroll 7
        for (int p = 0; p < P_; p++) {
            float w = s_ptit[t][p];
            float2 a = __half22float2(ip[p * (ISTR / 2)]);
            acc.x += w * a.x;
            acc.y += w * a.y;
        }
        *(__half2*)(out_img + (size_t)t * D_ + d2 * 2) = __floats2half2_rn(acc.x, acc.y);
    }
    // attn_tit[p, 2*d2..] = sum_t pimg[p][t] * tit[t][2*d2..]  (warp per p)
    __half* out_tit = attn + (size_t)IMG_TOK * D_ + (size_t)bl * P_ * D_ + h * DH_;
    for (int i = tid; i < P_ * 32; i += 256) {
        int p = i >> 5, d2 = i & 31;
        const __half2* tp = (const __half2*)s_tit + d2;
        float2 acc = make_float2(0.f, 0.f);
        #pragma unroll
        for (int t = 0; t < T_; t++) {
            float w = s_pimg[p][t];
            float2 a = __half22float2(tp[t * (ISTR / 2)]);
            acc.x += w * a.x;
            acc.y += w * a.y;
        }
        *(__half2*)(out_tit + (size_t)p * D_ + d2 * 2) = __floats2half2_rn(acc.x, acc.y);
    }
}

// ---------------- residual (fp16 hid) + LayerNorm: 4 warps/block, one token per warp ----------------
__global__ void __launch_bounds__(128) ln_res_kernel(
    const __half* __restrict__ hid, const float* __restrict__ ffn,
    const float* __restrict__ aimg, const float* __restrict__ bimg,
    const float* __restrict__ atit, const float* __restrict__ btit,
    float* __restrict__ out)
{
    int tok = blockIdx.x * 4 + (threadIdx.x >> 5);
    if (tok >= NTOK) return;
    const float* a  = (tok < IMG_TOK) ? aimg : atit;
    const float* bb = (tok < IMG_TOK) ? bimg : btit;
    const float* x  = ffn + (size_t)tok * D_;
    const __half* hh = hid + (size_t)tok * D_;
    float* o        = out + (size_t)tok * D_;

    int lane = threadIdx.x & 31;
    float v[16];
    float s = 0.f;
    #pragma unroll
    for (int i = 0; i < 4; i++) {
        float4 t4 = *(const float4*)(x + lane * 4 + i * 128);
        v[i*4+0] = t4.x; v[i*4+1] = t4.y; v[i*4+2] = t4.z; v[i*4+3] = t4.w;
        s += t4.x + t4.y + t4.z + t4.w;
    }
    #pragma unroll
    for (int off = 16; off > 0; off >>= 1) s += __shfl_xor_sync(0xffffffffu, s, off);
    float mean = s * (1.f / 512.f);

    float sq = 0.f;
    #pragma unroll
    for (int i = 0; i < 16; i++) { float d = v[i] - mean; sq += d * d; }
    #pragma unroll
    for (int off = 16; off > 0; off >>= 1) sq += __shfl_xor_sync(0xffffffffu, sq, off);
    float stdv = sqrtf(sq * (1.f / 511.f));
    float inv = 1.f / (stdv + EPS_);

    #pragma unroll
    for (int i = 0; i < 4; i++) {
        int c0 = lane * 4 + i * 128;
        float4 a4 = *(const float4*)(a  + c0);
        float4 b4 = *(const float4*)(bb + c0);
        __half2 h01 = *(const __half2*)(hh + c0);
        __half2 h23 = *(const __half2*)(hh + c0 + 2);
        float2 f01 = __half22float2(h01);
        float2 f23 = __half22float2(h23);
        float4 r;
        r.x = f01.x + a4.x * (v[i*4+0] - mean) * inv + b4.x;
        r.y = f01.y + a4.y * (v[i*4+1] - mean) * inv + b4.y;
        r.z = f23.x + a4.z * (v[i*4+2] - mean) * inv + b4.z;
        r.w = f23.y + a4.w * (v[i*4+3] - mean) * inv + b4.w;
        *(float4*)(o + c0) = r;
    }
}

// ---------------- launch ----------------
#define MTILES ((NTOK + 127) / 128)      // 432
#define SPLIT_TILE (IMG_TOK / 128)       // 125 (exact)

extern "C" void kernel_launch(void* const* d_in, const int* in_sizes, int n_in,
                              void* d_out, int out_size)
{
    const float* img         = (const float*)d_in[0];
    const float* title       = (const float*)d_in[1];
    const int*   mask        = (const int*)  d_in[2];
    const float* scale_img   = (const float*)d_in[3];
    const float* scale_title = (const float*)d_in[4];
    const float* w_proj      = (const float*)d_in[5];
    const float* b_proj      = (const float*)d_in[6];
    const float* w1_img      = (const float*)d_in[7];
    const float* b1_img      = (const float*)d_in[8];
    const float* w2_img      = (const float*)d_in[9];
    const float* b2_img      = (const float*)d_in[10];
    const float* w1_tit      = (const float*)d_in[11];
    const float* b1_tit      = (const float*)d_in[12];
    const float* w2_tit      = (const float*)d_in[13];
    const float* b2_tit      = (const float*)d_in[14];
    const float* ln_a_img    = (const float*)d_in[15];
    const float* ln_b_img    = (const float*)d_in[16];
    const float* ln_a_tit    = (const float*)d_in[17];
    const float* ln_b_tit    = (const float*)d_in[18];
    float* out = (float*)d_out;

    __half *attn_h, *hid_h, *ffn1_h, *wbuf;
    float *ffn2;
    cudaGetSymbolAddress((void**)&attn_h, g_attn_h);
    cudaGetSymbolAddress((void**)&hid_h,  g_hid_h);
    cudaGetSymbolAddress((void**)&ffn1_h, g_ffn1_h);
    cudaGetSymbolAddress((void**)&ffn2,   g_ffn2);
    cudaGetSymbolAddress((void**)&wbuf,   g_wbuf);

    cudaFuncSetAttribute(mma_gemm, cudaFuncAttributeMaxDynamicSharedMemorySize, MM_SMEM);

    // 0) weights -> fp16
    prep_w<<<(WTOTAL / 4 + 255) / 256, 256>>>(w_proj, w1_img, w1_tit, w2_img, w2_tit, wbuf);

    // 1) attention (writes fp16)
    attn_kernel<<<B_ * L_ * H_, 256>>>(img, title, mask, scale_img, scale_title, attn_h);

    // 2) shared projection: fp16 hid only (residual + FFN1 input)
    mma_gemm<<<dim3(D_ / 64, MTILES), 128, MM_SMEM>>>(
        attn_h, wbuf + WOFF_PROJ, b_proj, wbuf + WOFF_PROJ, b_proj, MTILES,
        (float*)nullptr, hid_h, NTOK, D_, D_, 0);

    // 3) FFN1 (+GELU), both branches, fp16 output only
    mma_gemm<<<dim3(DFF_ / 64, MTILES), 128, MM_SMEM>>>(
        hid_h, wbuf + WOFF_W1I, b1_img, wbuf + WOFF_W1T, b1_tit, SPLIT_TILE,
        (float*)nullptr, ffn1_h, NTOK, DFF_, D_, 1);

    // 4) FFN2, both branches, fp32 output only
    mma_gemm<<<dim3(D_ / 64, MTILES), 128, MM_SMEM>>>(
        ffn1_h, wbuf + WOFF_W2I, b2_img, wbuf + WOFF_W2T, b2_tit, SPLIT_TILE,
        ffn2, (__half*)nullptr, NTOK, D_, DFF_, 0);

    // 5) out = hid + LN(ffn2)
    ln_res_kernel<<<(NTOK + 3) / 4, 128>>>(hid_h, ffn2, ln_a_img, ln_b_img,
                                           ln_a_tit, ln_b_tit, out);
}